// round 1
// baseline (speedup 1.0000x reference)
#include <cuda_runtime.h>
#include <cuda_bf16.h>
#include <math.h>

// Problem constants
#define BB   2
#define TT   1024
#define CC   2048
#define NH   16
#define HS   128
#define NLQ  512
#define NLKV 512
#define DHR  64
#define KCAT 576   // NLKV + DHR

// ---------------- scratch (device globals; allocation-free) ----------------
__device__ float g_keff[16l * 512 * 512];       // [h][q][k]
__device__ float g_veff[512l * 2048];           // [k][h*HS+d]
__device__ float g_cq  [2048l * 512];           // [b*T+t][q]
__device__ float g_ckr [2048l * 64];            // [b*T+t][d]
__device__ float g_cqr [2048l * 1024];          // [b*T+t][h*64+d]
__device__ float g_kcat[2048l * 576];           // [b*T+t][0:512]=c_kv, [512:576]=k_r
__device__ float g_qcat[32l * 1024 * 576];      // [b*16+h][t][0:512]=q_abs, [512:]=q_r
__device__ float g_attn[32l * 1024 * 1024];     // [b*16+h][t][s]
__device__ float g_lat [32l * 1024 * 512];      // [b*16+h][t][k]

// ---------------- generic strided batched SGEMM ----------------
// C[m,n] = sum_k A[aOff + m*sAm + k*sAk] * B[bOff + k*sBk + n*sBn]
// batch offsets: off = (z/div)*s1 + (z%mod)*s2
struct GP {
    const float* A; const float* B; float* C;
    int M, N, K;
    long sAm, sAk, sBk, sBn, ldc;
    int aDiv, aMod, bDiv, bMod, cDiv, cMod;
    long aS1, aS2, bS1, bS2, cS1, cS2;
};

__global__ __launch_bounds__(256) void sgemm128(GP p) {
    int z = blockIdx.z;
    const float* A = p.A + (long)(z / p.aDiv) * p.aS1 + (long)(z % p.aMod) * p.aS2;
    const float* B = p.B + (long)(z / p.bDiv) * p.bS1 + (long)(z % p.bMod) * p.bS2;
    float*       C = p.C + (long)(z / p.cDiv) * p.cS1 + (long)(z % p.cMod) * p.cS2;

    __shared__ float As[8][128];
    __shared__ float Bs[8][128];

    int tid = threadIdx.x;
    int tx = tid & 15, ty = tid >> 4;
    int bm = blockIdx.y * 128, bn = blockIdx.x * 128;

    float acc[8][8];
#pragma unroll
    for (int i = 0; i < 8; i++)
#pragma unroll
        for (int j = 0; j < 8; j++) acc[i][j] = 0.f;

    for (int k0 = 0; k0 < p.K; k0 += 8) {
#pragma unroll
        for (int i = 0; i < 4; i++) {
            int e = tid + i * 256;
            int r = e >> 3, c = e & 7;
            int gm = bm + r, gk = k0 + c;
            As[c][r] = (gm < p.M && gk < p.K)
                       ? A[(long)gm * p.sAm + (long)gk * p.sAk] : 0.f;
        }
#pragma unroll
        for (int i = 0; i < 4; i++) {
            int e = tid + i * 256;
            int kk = e >> 7, c = e & 127;
            int gk = k0 + kk, gn = bn + c;
            Bs[kk][c] = (gk < p.K && gn < p.N)
                        ? B[(long)gk * p.sBk + (long)gn * p.sBn] : 0.f;
        }
        __syncthreads();
#pragma unroll
        for (int kk = 0; kk < 8; kk++) {
            float a[8], b[8];
#pragma unroll
            for (int i = 0; i < 8; i++) a[i] = As[kk][ty * 8 + i];
#pragma unroll
            for (int j = 0; j < 8; j++) b[j] = Bs[kk][tx * 8 + j];
#pragma unroll
            for (int i = 0; i < 8; i++)
#pragma unroll
                for (int j = 0; j < 8; j++)
                    acc[i][j] += a[i] * b[j];
        }
        __syncthreads();
    }

#pragma unroll
    for (int i = 0; i < 8; i++) {
        int gm = bm + ty * 8 + i;
        if (gm >= p.M) continue;
#pragma unroll
        for (int j = 0; j < 8; j++) {
            int gn = bn + tx * 8 + j;
            if (gn < p.N) C[(long)gm * p.ldc + gn] = acc[i][j];
        }
    }
}

// ---------------- RoPE kernels ----------------
__global__ void rope_k_kernel(const float* __restrict__ ckr,
                              const float* __restrict__ fc,
                              const float* __restrict__ fs,
                              float* __restrict__ kcat) {
    int idx = blockIdx.x * blockDim.x + threadIdx.x;   // over 2048*32
    if (idx >= 2048 * 32) return;
    int m = idx >> 5, i = idx & 31;
    int t = m & 1023;
    float re = ckr[m * 64 + 2 * i], im = ckr[m * 64 + 2 * i + 1];
    float c = fc[t * 32 + i], s = fs[t * 32 + i];
    long o = (long)m * KCAT + 512 + 2 * i;
    kcat[o]     = re * c - im * s;
    kcat[o + 1] = re * s + im * c;
}

__global__ void rope_q_kernel(const float* __restrict__ cqr,
                              const float* __restrict__ fc,
                              const float* __restrict__ fs,
                              float* __restrict__ qcat) {
    int idx = blockIdx.x * blockDim.x + threadIdx.x;   // over 2048*16*32
    if (idx >= 2048 * 16 * 32) return;
    int i = idx & 31;
    int h = (idx >> 5) & 15;
    int m = idx >> 9;            // b*1024 + t
    int t = m & 1023, b = m >> 10;
    float re = cqr[m * 1024 + h * 64 + 2 * i];
    float im = cqr[m * 1024 + h * 64 + 2 * i + 1];
    float c = fc[t * 32 + i], s = fs[t * 32 + i];
    long o = ((long)((b * 16 + h) * 1024 + t)) * KCAT + 512 + 2 * i;
    qcat[o]     = re * c - im * s;
    qcat[o + 1] = re * s + im * c;
}

// ---------------- causal softmax (in-place on logits) ----------------
__global__ void softmax_causal(float* __restrict__ attn) {
    int t = blockIdx.x;
    int z = blockIdx.y;
    float* p = attn + (long)z * 1024 * 1024 + (long)t * 1024;
    int n = t + 1;
    const float scale = 0.07216878364870322992f;  // 1/sqrt(HS+DHR)=1/sqrt(192)
    __shared__ float red[256];
    int tid = threadIdx.x;

    float m = -3.4e38f;
    for (int s = tid; s < n; s += 256) m = fmaxf(m, p[s] * scale);
    red[tid] = m; __syncthreads();
    for (int o = 128; o > 0; o >>= 1) {
        if (tid < o) red[tid] = fmaxf(red[tid], red[tid + o]);
        __syncthreads();
    }
    m = red[0]; __syncthreads();

    float sum = 0.f;
    for (int s = tid; s < n; s += 256) sum += expf(p[s] * scale - m);
    red[tid] = sum; __syncthreads();
    for (int o = 128; o > 0; o >>= 1) {
        if (tid < o) red[tid] += red[tid + o];
        __syncthreads();
    }
    float inv = 1.f / red[0];
    __syncthreads();

    for (int s = tid; s < 1024; s += 256)
        p[s] = (s < n) ? expf(p[s] * scale - m) * inv : 0.f;
}

// ---------------- host-side launch helper ----------------
static void launch_gemm(const float* A, const float* B, float* C,
                        int M, int N, int K,
                        long sAm, long sAk, long sBk, long sBn, long ldc,
                        int batches,
                        int aDiv, long aS1, int aMod, long aS2,
                        int bDiv, long bS1, int bMod, long bS2,
                        int cDiv, long cS1, int cMod, long cS2) {
    GP p;
    p.A = A; p.B = B; p.C = C;
    p.M = M; p.N = N; p.K = K;
    p.sAm = sAm; p.sAk = sAk; p.sBk = sBk; p.sBn = sBn; p.ldc = ldc;
    p.aDiv = aDiv; p.aMod = aMod; p.bDiv = bDiv; p.bMod = bMod;
    p.cDiv = cDiv; p.cMod = cMod;
    p.aS1 = aS1; p.aS2 = aS2; p.bS1 = bS1; p.bS2 = bS2; p.cS1 = cS1; p.cS2 = cS2;
    dim3 grid((N + 127) / 128, (M + 127) / 128, batches);
    sgemm128<<<grid, 256>>>(p);
}

extern "C" void kernel_launch(void* const* d_in, const int* in_sizes, int n_in,
                              void* d_out, int out_size) {
    const float* x     = (const float*)d_in[0];
    const float* fcos  = (const float*)d_in[1];
    const float* fsin  = (const float*)d_in[2];
    const float* W_dq  = (const float*)d_in[3];
    const float* W_uq  = (const float*)d_in[4];
    const float* W_dkv = (const float*)d_in[5];
    const float* W_uk  = (const float*)d_in[6];
    const float* W_uv  = (const float*)d_in[7];
    const float* W_qr  = (const float*)d_in[8];
    const float* W_kr  = (const float*)d_in[9];
    const float* W_o   = (const float*)d_in[10];
    float* out = (float*)d_out;

    float *keff, *veff, *cq, *ckr, *cqr, *kcat, *qcat, *attn, *lat;
    cudaGetSymbolAddress((void**)&keff, g_keff);
    cudaGetSymbolAddress((void**)&veff, g_veff);
    cudaGetSymbolAddress((void**)&cq,   g_cq);
    cudaGetSymbolAddress((void**)&ckr,  g_ckr);
    cudaGetSymbolAddress((void**)&cqr,  g_cqr);
    cudaGetSymbolAddress((void**)&kcat, g_kcat);
    cudaGetSymbolAddress((void**)&qcat, g_qcat);
    cudaGetSymbolAddress((void**)&attn, g_attn);
    cudaGetSymbolAddress((void**)&lat,  g_lat);

    // 1) k_eff[h][q][k] = sum_d Wuq_flat[q*2048 + h*128 + d] * W_uk[(h*128+d)*512 + k]
    launch_gemm(W_uq, W_uk, keff, 512, 512, 128,
                2048, 1, 512, 1, 512, 16,
                1, 0, 16, 128,
                1, 0, 16, 128l * 512,
                1, 0, 16, 512l * 512);

    // 2) v_eff[k][j] = sum_c W_uv[c*512+k] * W_o[j*2048+c]
    launch_gemm(W_uv, W_o, veff, 512, 2048, 2048,
                1, 512, 1, 2048, 2048, 1,
                1, 0, 1, 0, 1, 0, 1, 0, 1, 0, 1, 0);

    // 3) c_q = x @ W_dq^T   (M=B*T=2048)
    launch_gemm(x, W_dq, cq, 2048, 512, 2048,
                2048, 1, 1, 2048, 512, 1,
                1, 0, 1, 0, 1, 0, 1, 0, 1, 0, 1, 0);

    // 4) c_kv = x @ W_dkv^T  -> k_cat columns [0,512), row stride 576
    launch_gemm(x, W_dkv, kcat, 2048, 512, 2048,
                2048, 1, 1, 2048, KCAT, 1,
                1, 0, 1, 0, 1, 0, 1, 0, 1, 0, 1, 0);

    // 5) c_kr = x @ W_kr^T   (M=2048, N=64)
    launch_gemm(x, W_kr, ckr, 2048, 64, 2048,
                2048, 1, 1, 2048, 64, 1,
                1, 0, 1, 0, 1, 0, 1, 0, 1, 0, 1, 0);

    // 6) c_qr = c_q @ W_qr^T (M=2048, N=1024, K=512)
    launch_gemm(cq, W_qr, cqr, 2048, 1024, 512,
                512, 1, 1, 512, 1024, 1,
                1, 0, 1, 0, 1, 0, 1, 0, 1, 0, 1, 0);

    // 7) RoPE k -> k_cat cols [512,576)
    rope_k_kernel<<<(2048 * 32 + 255) / 256, 256>>>(ckr, fcos, fsin, kcat);
    // 8) RoPE q -> q_cat cols [512,576)
    rope_q_kernel<<<(2048 * 16 * 32 + 255) / 256, 256>>>(cqr, fcos, fsin, qcat);

    // 9) q_abs[b,h] = c_q[b] @ k_eff[h]  -> q_cat cols [0,512)   (32 batches, z=b*16+h)
    launch_gemm(cq, keff, qcat, 1024, 512, 512,
                512, 1, 512, 1, KCAT, 32,
                16, 1024l * 512, 1, 0,
                1, 0, 16, 512l * 512,
                1, 0, 32, 1024l * KCAT);

    // 10) logits = q_cat @ k_cat^T  (K=576 fuses content + rope parts)
    launch_gemm(qcat, kcat, attn, 1024, 1024, KCAT,
                KCAT, 1, 1, KCAT, 1024, 32,
                1, 0, 32, 1024l * KCAT,
                16, 1024l * KCAT, 1, 0,
                1, 0, 32, 1024l * 1024);

    // 11) causal softmax in-place
    {
        dim3 grid(1024, 32);
        softmax_causal<<<grid, 256>>>(attn);
    }

    // 12) lat = attn @ c_kv  (B rows from k_cat cols [0,512), row stride 576)
    launch_gemm(attn, kcat, lat, 1024, 512, 1024,
                1024, 1, KCAT, 1, 512, 32,
                1, 0, 32, 1024l * 1024,
                16, 1024l * KCAT, 1, 0,
                1, 0, 32, 1024l * 512);

    // 13) y[b,t,h*128+d] = sum_k lat[b,h,t,k] * v_eff[k][h*128+d]
    launch_gemm(lat, veff, out, 1024, 128, 512,
                512, 1, 2048, 1, 2048, 32,
                1, 0, 32, 1024l * 512,
                1, 0, 16, 128,
                16, 1024l * 2048, 16, 128);
}

// round 2
// speedup vs baseline: 1.1827x; 1.1827x over previous
#include <cuda_runtime.h>
#include <cuda_bf16.h>
#include <math.h>

// Problem constants
#define BB   2
#define TT   1024
#define CC   2048
#define NH   16
#define HS   128
#define NLQ  512
#define NLKV 512
#define DHR  64
#define KCAT 576   // NLKV + DHR

// ---------------- scratch (device globals; allocation-free) ----------------
__device__ float g_keff[16l * 512 * 512];       // [h][q][k]
__device__ float g_veff[512l * 2048];           // [k][h*HS+d]
__device__ float g_cq  [2048l * 512];           // [b*T+t][q]
__device__ float g_ckr [2048l * 64];            // [b*T+t][d]
__device__ float g_cqr [2048l * 1024];          // [b*T+t][h*64+d]
__device__ float g_kcat[2048l * 576];           // [b*T+t][0:512]=c_kv, [512:576]=k_r
__device__ float g_qcat[32l * 1024 * 576];      // [b*16+h][t][0:512]=q_abs, [512:]=q_r
__device__ float g_attn[32l * 1024 * 1024];     // [b*16+h][t][s]
__device__ float g_lat [32l * 1024 * 512];      // [b*16+h][t][k]

// ---------------- generic strided batched GEMM params ----------------
// C[m,n] = sum_k A[m*sAm + k*sAk] * B[k*sBk + n*sBn], batch offsets via div/mod
struct GP {
    const float* A; const float* B; float* C;
    int M, N, K;
    long sAm, sAk, sBk, sBn, ldc;
    int aDiv, aMod, bDiv, bMod, cDiv, cMod;
    long aS1, aS2, bS1, bS2, cS1, cS2;
};

__device__ __forceinline__ unsigned f2tf32(float x) {
    unsigned u;
    asm("cvt.rna.tf32.f32 %0, %1;" : "=r"(u) : "f"(x));
    return u;
}

__device__ __forceinline__ void mma_tf32(float* d, const unsigned* a,
                                         const unsigned* b) {
    asm volatile(
        "mma.sync.aligned.m16n8k8.row.col.f32.tf32.tf32.f32 "
        "{%0,%1,%2,%3}, {%4,%5,%6,%7}, {%8,%9}, {%0,%1,%2,%3};\n"
        : "+f"(d[0]), "+f"(d[1]), "+f"(d[2]), "+f"(d[3])
        : "r"(a[0]), "r"(a[1]), "r"(a[2]), "r"(a[3]),
          "r"(b[0]), "r"(b[1]));
}

#define SPAD 136   // smem row stride in words; %32 == 8 -> conflict-free frags

// Tensor-core TF32 GEMM: block tile 128x128x16, 8 warps (2m x 4n),
// warp tile 64x32, mma m16n8k8, fp32 accumulate.
__global__ __launch_bounds__(256) void tgemm(GP p) {
    int z = blockIdx.z;
    const float* A = p.A + (long)(z / p.aDiv) * p.aS1 + (long)(z % p.aMod) * p.aS2;
    const float* B = p.B + (long)(z / p.bDiv) * p.bS1 + (long)(z % p.bMod) * p.bS2;
    float*       C = p.C + (long)(z / p.cDiv) * p.cS1 + (long)(z % p.cMod) * p.cS2;

    __shared__ unsigned As[16][SPAD];   // [k][m]
    __shared__ unsigned Bs[16][SPAD];   // [k][n]

    int tid  = threadIdx.x;
    int lane = tid & 31;
    int wid  = tid >> 5;
    int wm = wid >> 2;          // 0..1
    int wn = wid & 3;           // 0..3
    int bm = blockIdx.y * 128, bn = blockIdx.x * 128;

    const bool aKcontig = (p.sAk == 1);
    const bool bKcontig = (p.sBk == 1);

    float acc[4][4][4];
#pragma unroll
    for (int i = 0; i < 4; i++)
#pragma unroll
        for (int j = 0; j < 4; j++)
#pragma unroll
            for (int r = 0; r < 4; r++) acc[i][j][r] = 0.f;

    for (int k0 = 0; k0 < p.K; k0 += 16) {
        // ---- load A tile (128m x 16k) ----
        if (aKcontig) {
            int m  = tid & 127;
            int ks = (tid >> 7) * 8;
            const float* ap = A + (long)(bm + m) * p.sAm + (k0 + ks);
#pragma unroll
            for (int j = 0; j < 8; j++) As[ks + j][m] = f2tf32(ap[j]);
        } else {  // sAm == 1, m contiguous
            int kk = tid & 15;
            int m0 = (tid >> 4) * 8;
            const float* ap = A + (long)(k0 + kk) * p.sAk + (bm + m0);
#pragma unroll
            for (int j = 0; j < 8; j++) As[kk][m0 + j] = f2tf32(ap[j]);
        }
        // ---- load B tile (16k x 128n) ----
        if (bKcontig) {
            int n  = tid & 127;
            int ks = (tid >> 7) * 8;
            int gn = bn + n;
            const float* bp = B + (long)gn * p.sBn + (k0 + ks);
            bool ok = (gn < p.N);
#pragma unroll
            for (int j = 0; j < 8; j++) Bs[ks + j][n] = ok ? f2tf32(bp[j]) : 0u;
        } else {  // sBn == 1, n contiguous
            int kk = tid & 15;
            int n0 = (tid >> 4) * 8;
            const float* bp = B + (long)(k0 + kk) * p.sBk + (bn + n0);
#pragma unroll
            for (int j = 0; j < 8; j++) {
                int gn = bn + n0 + j;
                Bs[kk][n0 + j] = (gn < p.N) ? f2tf32(bp[j]) : 0u;
            }
        }
        __syncthreads();

        int r = lane >> 2, c = lane & 3;
#pragma unroll
        for (int ks = 0; ks < 16; ks += 8) {
            unsigned a[4][4], b[4][2];
#pragma unroll
            for (int mi = 0; mi < 4; mi++) {
                int m = wm * 64 + mi * 16 + r;
                a[mi][0] = As[ks + c][m];
                a[mi][1] = As[ks + c][m + 8];
                a[mi][2] = As[ks + 4 + c][m];
                a[mi][3] = As[ks + 4 + c][m + 8];
            }
#pragma unroll
            for (int ni = 0; ni < 4; ni++) {
                int n = wn * 32 + ni * 8 + r;
                b[ni][0] = Bs[ks + c][n];
                b[ni][1] = Bs[ks + 4 + c][n];
            }
#pragma unroll
            for (int mi = 0; mi < 4; mi++)
#pragma unroll
                for (int ni = 0; ni < 4; ni++)
                    mma_tf32(acc[mi][ni], a[mi], b[ni]);
        }
        __syncthreads();
    }

    // ---- store C ----
    int r = lane >> 2, c2 = (lane & 3) * 2;
#pragma unroll
    for (int mi = 0; mi < 4; mi++) {
        int gm0 = bm + wm * 64 + mi * 16 + r;
#pragma unroll
        for (int ni = 0; ni < 4; ni++) {
            int gn = bn + wn * 32 + ni * 8 + c2;
            float* cp0 = C + (long)gm0 * p.ldc + gn;
            float* cp1 = C + (long)(gm0 + 8) * p.ldc + gn;
            if (gn < p.N)     { cp0[0] = acc[mi][ni][0]; cp1[0] = acc[mi][ni][2]; }
            if (gn + 1 < p.N) { cp0[1] = acc[mi][ni][1]; cp1[1] = acc[mi][ni][3]; }
        }
    }
}

// ---------------- RoPE kernels ----------------
__global__ void rope_k_kernel(const float* __restrict__ ckr,
                              const float* __restrict__ fc,
                              const float* __restrict__ fs,
                              float* __restrict__ kcat) {
    int idx = blockIdx.x * blockDim.x + threadIdx.x;
    if (idx >= 2048 * 32) return;
    int m = idx >> 5, i = idx & 31;
    int t = m & 1023;
    float re = ckr[m * 64 + 2 * i], im = ckr[m * 64 + 2 * i + 1];
    float c = fc[t * 32 + i], s = fs[t * 32 + i];
    long o = (long)m * KCAT + 512 + 2 * i;
    kcat[o]     = re * c - im * s;
    kcat[o + 1] = re * s + im * c;
}

__global__ void rope_q_kernel(const float* __restrict__ cqr,
                              const float* __restrict__ fc,
                              const float* __restrict__ fs,
                              float* __restrict__ qcat) {
    int idx = blockIdx.x * blockDim.x + threadIdx.x;
    if (idx >= 2048 * 16 * 32) return;
    int i = idx & 31;
    int h = (idx >> 5) & 15;
    int m = idx >> 9;
    int t = m & 1023, b = m >> 10;
    float re = cqr[m * 1024 + h * 64 + 2 * i];
    float im = cqr[m * 1024 + h * 64 + 2 * i + 1];
    float c = fc[t * 32 + i], s = fs[t * 32 + i];
    long o = ((long)((b * 16 + h) * 1024 + t)) * KCAT + 512 + 2 * i;
    qcat[o]     = re * c - im * s;
    qcat[o + 1] = re * s + im * c;
}

// ---------------- causal softmax (in-place on logits) ----------------
__global__ void softmax_causal(float* __restrict__ attn) {
    int t = blockIdx.x;
    int z = blockIdx.y;
    float* p = attn + (long)z * 1024 * 1024 + (long)t * 1024;
    int n = t + 1;
    const float scale = 0.07216878364870322992f;  // 1/sqrt(192)
    __shared__ float red[256];
    int tid = threadIdx.x;

    float m = -3.4e38f;
    for (int s = tid; s < n; s += 256) m = fmaxf(m, p[s] * scale);
    red[tid] = m; __syncthreads();
    for (int o = 128; o > 0; o >>= 1) {
        if (tid < o) red[tid] = fmaxf(red[tid], red[tid + o]);
        __syncthreads();
    }
    m = red[0]; __syncthreads();

    float sum = 0.f;
    for (int s = tid; s < n; s += 256) sum += expf(p[s] * scale - m);
    red[tid] = sum; __syncthreads();
    for (int o = 128; o > 0; o >>= 1) {
        if (tid < o) red[tid] += red[tid + o];
        __syncthreads();
    }
    float inv = 1.f / red[0];
    __syncthreads();

    for (int s = tid; s < 1024; s += 256)
        p[s] = (s < n) ? expf(p[s] * scale - m) * inv : 0.f;
}

// ---------------- host-side launch helper ----------------
static void launch_gemm(const float* A, const float* B, float* C,
                        int M, int N, int K,
                        long sAm, long sAk, long sBk, long sBn, long ldc,
                        int batches,
                        int aDiv, long aS1, int aMod, long aS2,
                        int bDiv, long bS1, int bMod, long bS2,
                        int cDiv, long cS1, int cMod, long cS2) {
    GP p;
    p.A = A; p.B = B; p.C = C;
    p.M = M; p.N = N; p.K = K;
    p.sAm = sAm; p.sAk = sAk; p.sBk = sBk; p.sBn = sBn; p.ldc = ldc;
    p.aDiv = aDiv; p.aMod = aMod; p.bDiv = bDiv; p.bMod = bMod;
    p.cDiv = cDiv; p.cMod = cMod;
    p.aS1 = aS1; p.aS2 = aS2; p.bS1 = bS1; p.bS2 = bS2; p.cS1 = cS1; p.cS2 = cS2;
    dim3 grid((N + 127) / 128, (M + 127) / 128, batches);
    tgemm<<<grid, 256>>>(p);
}

extern "C" void kernel_launch(void* const* d_in, const int* in_sizes, int n_in,
                              void* d_out, int out_size) {
    const float* x     = (const float*)d_in[0];
    const float* fcos  = (const float*)d_in[1];
    const float* fsin  = (const float*)d_in[2];
    const float* W_dq  = (const float*)d_in[3];
    const float* W_uq  = (const float*)d_in[4];
    const float* W_dkv = (const float*)d_in[5];
    const float* W_uk  = (const float*)d_in[6];
    const float* W_uv  = (const float*)d_in[7];
    const float* W_qr  = (const float*)d_in[8];
    const float* W_kr  = (const float*)d_in[9];
    const float* W_o   = (const float*)d_in[10];
    float* out = (float*)d_out;

    float *keff, *veff, *cq, *ckr, *cqr, *kcat, *qcat, *attn, *lat;
    cudaGetSymbolAddress((void**)&keff, g_keff);
    cudaGetSymbolAddress((void**)&veff, g_veff);
    cudaGetSymbolAddress((void**)&cq,   g_cq);
    cudaGetSymbolAddress((void**)&ckr,  g_ckr);
    cudaGetSymbolAddress((void**)&cqr,  g_cqr);
    cudaGetSymbolAddress((void**)&kcat, g_kcat);
    cudaGetSymbolAddress((void**)&qcat, g_qcat);
    cudaGetSymbolAddress((void**)&attn, g_attn);
    cudaGetSymbolAddress((void**)&lat,  g_lat);

    // 1) k_eff[h][q][k] = sum_d Wuq_flat[q*2048 + h*128 + d] * W_uk[(h*128+d)*512 + k]
    launch_gemm(W_uq, W_uk, keff, 512, 512, 128,
                2048, 1, 512, 1, 512, 16,
                1, 0, 16, 128,
                1, 0, 16, 128l * 512,
                1, 0, 16, 512l * 512);

    // 2) v_eff[k][j] = sum_c W_uv[c*512+k] * W_o[j*2048+c]
    launch_gemm(W_uv, W_o, veff, 512, 2048, 2048,
                1, 512, 1, 2048, 2048, 1,
                1, 0, 1, 0, 1, 0, 1, 0, 1, 0, 1, 0);

    // 3) c_q = x @ W_dq^T
    launch_gemm(x, W_dq, cq, 2048, 512, 2048,
                2048, 1, 1, 2048, 512, 1,
                1, 0, 1, 0, 1, 0, 1, 0, 1, 0, 1, 0);

    // 4) c_kv = x @ W_dkv^T  -> k_cat cols [0,512), row stride 576
    launch_gemm(x, W_dkv, kcat, 2048, 512, 2048,
                2048, 1, 1, 2048, KCAT, 1,
                1, 0, 1, 0, 1, 0, 1, 0, 1, 0, 1, 0);

    // 5) c_kr = x @ W_kr^T
    launch_gemm(x, W_kr, ckr, 2048, 64, 2048,
                2048, 1, 1, 2048, 64, 1,
                1, 0, 1, 0, 1, 0, 1, 0, 1, 0, 1, 0);

    // 6) c_qr = c_q @ W_qr^T
    launch_gemm(cq, W_qr, cqr, 2048, 1024, 512,
                512, 1, 1, 512, 1024, 1,
                1, 0, 1, 0, 1, 0, 1, 0, 1, 0, 1, 0);

    // 7) RoPE k -> k_cat cols [512,576)
    rope_k_kernel<<<(2048 * 32 + 255) / 256, 256>>>(ckr, fcos, fsin, kcat);
    // 8) RoPE q -> q_cat cols [512,576)
    rope_q_kernel<<<(2048 * 16 * 32 + 255) / 256, 256>>>(cqr, fcos, fsin, qcat);

    // 9) q_abs[b,h] = c_q[b] @ k_eff[h]  -> q_cat cols [0,512)
    launch_gemm(cq, keff, qcat, 1024, 512, 512,
                512, 1, 512, 1, KCAT, 32,
                16, 1024l * 512, 1, 0,
                1, 0, 16, 512l * 512,
                1, 0, 32, 1024l * KCAT);

    // 10) logits = q_cat @ k_cat^T  (K=576 fuses content + rope)
    launch_gemm(qcat, kcat, attn, 1024, 1024, KCAT,
                KCAT, 1, 1, KCAT, 1024, 32,
                1, 0, 32, 1024l * KCAT,
                16, 1024l * KCAT, 1, 0,
                1, 0, 32, 1024l * 1024);

    // 11) causal softmax in-place
    {
        dim3 grid(1024, 32);
        softmax_causal<<<grid, 256>>>(attn);
    }

    // 12) lat = attn @ c_kv
    launch_gemm(attn, kcat, lat, 1024, 512, 1024,
                1024, 1, KCAT, 1, 512, 32,
                1, 0, 32, 1024l * 1024,
                16, 1024l * KCAT, 1, 0,
                1, 0, 32, 1024l * 512);

    // 13) y[b,t,h*128+d] = sum_k lat[b,h,t,k] * v_eff[k][h*128+d]
    launch_gemm(lat, veff, out, 1024, 128, 512,
                512, 1, 2048, 1, 2048, 32,
                1, 0, 32, 1024l * 512,
                1, 0, 16, 128,
                16, 1024l * 2048, 16, 128);
}

// round 3
// speedup vs baseline: 1.5870x; 1.3419x over previous
#include <cuda_runtime.h>
#include <cuda_bf16.h>
#include <math.h>

// Problem constants
#define BB   2
#define TT   1024
#define CC   2048
#define NH   16
#define HS   128
#define NLQ  512
#define NLKV 512
#define DHR  64
#define KCAT 576   // NLKV + DHR

// ---------------- scratch (device globals; allocation-free) ----------------
__device__ float g_keff[16l * 512 * 512];
__device__ float g_veff[512l * 2048];
__device__ float g_cq  [2048l * 512];
__device__ float g_ckr [2048l * 64];
__device__ float g_cqr [2048l * 1024];
__device__ float g_kcat[2048l * 576];
__device__ float g_qcat[32l * 1024 * 576];
__device__ float g_attn[32l * 1024 * 1024];
__device__ float g_lat [32l * 1024 * 512];

struct GP {
    const float* A; const float* B; float* C;
    int M, N, K;
    long sAm, sAk, sBk, sBn, ldc;
    int aDiv, aMod, bDiv, bMod, cDiv, cMod;
    long aS1, aS2, bS1, bS2, cS1, cS2;
};

__device__ __forceinline__ unsigned f2tf32(float x) {
    unsigned u;
    asm("cvt.rna.tf32.f32 %0, %1;" : "=r"(u) : "f"(x));
    return u;
}

__device__ __forceinline__ void mma_tf32(float* d, const unsigned* a,
                                         const unsigned* b) {
    asm volatile(
        "mma.sync.aligned.m16n8k8.row.col.f32.tf32.tf32.f32 "
        "{%0,%1,%2,%3}, {%4,%5,%6,%7}, {%8,%9}, {%0,%1,%2,%3};\n"
        : "+f"(d[0]), "+f"(d[1]), "+f"(d[2]), "+f"(d[3])
        : "r"(a[0]), "r"(a[1]), "r"(a[2]), "r"(a[3]),
          "r"(b[0]), "r"(b[1]));
}

#define SPAD 136   // %32==8 -> conflict-free fragment reads

// TF32 tensor-core GEMM, block tile 128x128x16, double-buffered smem,
// register-staged global prefetch, 8 warps (2m x 4n), warp tile 64x32.
__global__ __launch_bounds__(256) void tgemm(GP p) {
    int z = blockIdx.z;
    const float* A = p.A + (long)(z / p.aDiv) * p.aS1 + (long)(z % p.aMod) * p.aS2;
    const float* B = p.B + (long)(z / p.bDiv) * p.bS1 + (long)(z % p.bMod) * p.bS2;
    float*       C = p.C + (long)(z / p.cDiv) * p.cS1 + (long)(z % p.cMod) * p.cS2;

    __shared__ unsigned As[2][16][SPAD];
    __shared__ unsigned Bs[2][16][SPAD];

    int tid  = threadIdx.x;
    int lane = tid & 31;
    int wid  = tid >> 5;
    int wm = wid >> 2;
    int wn = wid & 3;
    int bm = blockIdx.y * 128, bn = blockIdx.x * 128;

    const bool aKc = (p.sAk == 1);
    const bool bKc = (p.sBk == 1);

    // per-thread staging indices (uniform across tiles)
    int a_i0, a_i1;            // smem row/col indices for A
    const float* aBase;
    long aStep;                // address step per k-tile (in floats)
    if (aKc) {
        a_i1 = tid & 127;              // m
        a_i0 = (tid >> 7) * 8;         // k start
        aBase = A + (long)(bm + a_i1) * p.sAm + a_i0;
        aStep = 16;
    } else {
        a_i0 = tid & 15;               // k
        a_i1 = (tid >> 4) * 8;         // m start
        aBase = A + (long)a_i0 * p.sAk + (bm + a_i1);
        aStep = 16 * p.sAk;
    }
    int b_i0, b_i1;
    const float* bBase;
    long bStep;
    bool bOk;
    if (bKc) {
        b_i1 = tid & 127;              // n
        b_i0 = (tid >> 7) * 8;         // k start
        bOk = (bn + b_i1) < p.N;
        bBase = B + (long)(bn + b_i1) * p.sBn + b_i0;
        bStep = 16;
    } else {
        b_i0 = tid & 15;               // k
        b_i1 = (tid >> 4) * 8;         // n start
        bOk = (bn + b_i1) < p.N;       // N%8==0 in all uses
        bBase = B + (long)b_i0 * p.sBk + (bn + b_i1);
        bStep = 16 * p.sBk;
    }

    float ra[8], rb[8];

#define LOAD_STAGE(t)                                                        \
    {                                                                        \
        const float* ap = aBase + (long)(t) * aStep;                         \
        float4 v0 = *(const float4*)ap;                                      \
        float4 v1 = *(const float4*)(ap + 4);                                \
        ra[0]=v0.x; ra[1]=v0.y; ra[2]=v0.z; ra[3]=v0.w;                      \
        ra[4]=v1.x; ra[5]=v1.y; ra[6]=v1.z; ra[7]=v1.w;                      \
        if (bOk) {                                                           \
            const float* bp = bBase + (long)(t) * bStep;                     \
            float4 w0 = *(const float4*)bp;                                  \
            float4 w1 = *(const float4*)(bp + 4);                            \
            rb[0]=w0.x; rb[1]=w0.y; rb[2]=w0.z; rb[3]=w0.w;                  \
            rb[4]=w1.x; rb[5]=w1.y; rb[6]=w1.z; rb[7]=w1.w;                  \
        } else {                                                             \
            rb[0]=rb[1]=rb[2]=rb[3]=rb[4]=rb[5]=rb[6]=rb[7]=0.f;             \
        }                                                                    \
    }

#define STORE_STAGE(buf)                                                     \
    {                                                                        \
        if (aKc) {                                                           \
            _Pragma("unroll")                                                \
            for (int j = 0; j < 8; j++)                                      \
                As[buf][a_i0 + j][a_i1] = f2tf32(ra[j]);                     \
        } else {                                                             \
            _Pragma("unroll")                                                \
            for (int j = 0; j < 8; j++)                                      \
                As[buf][a_i0][a_i1 + j] = f2tf32(ra[j]);                     \
        }                                                                    \
        if (bKc) {                                                           \
            _Pragma("unroll")                                                \
            for (int j = 0; j < 8; j++)                                      \
                Bs[buf][b_i0 + j][b_i1] = f2tf32(rb[j]);                     \
        } else {                                                             \
            _Pragma("unroll")                                                \
            for (int j = 0; j < 8; j++)                                      \
                Bs[buf][b_i0][b_i1 + j] = f2tf32(rb[j]);                     \
        }                                                                    \
    }

    float acc[4][4][4];
#pragma unroll
    for (int i = 0; i < 4; i++)
#pragma unroll
        for (int j = 0; j < 4; j++)
#pragma unroll
            for (int r = 0; r < 4; r++) acc[i][j][r] = 0.f;

    int nt = p.K >> 4;   // K % 16 == 0 in all uses

    LOAD_STAGE(0);
    STORE_STAGE(0);
    __syncthreads();

    int r = lane >> 2, c = lane & 3;

    for (int t = 0; t < nt; t++) {
        int cur = t & 1;
        if (t + 1 < nt) LOAD_STAGE(t + 1);

#pragma unroll
        for (int ks = 0; ks < 16; ks += 8) {
            unsigned a[4][4], b[4][2];
#pragma unroll
            for (int mi = 0; mi < 4; mi++) {
                int m = wm * 64 + mi * 16 + r;
                a[mi][0] = As[cur][ks + c][m];
                a[mi][1] = As[cur][ks + c][m + 8];
                a[mi][2] = As[cur][ks + 4 + c][m];
                a[mi][3] = As[cur][ks + 4 + c][m + 8];
            }
#pragma unroll
            for (int ni = 0; ni < 4; ni++) {
                int n = wn * 32 + ni * 8 + r;
                b[ni][0] = Bs[cur][ks + c][n];
                b[ni][1] = Bs[cur][ks + 4 + c][n];
            }
#pragma unroll
            for (int mi = 0; mi < 4; mi++)
#pragma unroll
                for (int ni = 0; ni < 4; ni++)
                    mma_tf32(acc[mi][ni], a[mi], b[ni]);
        }

        if (t + 1 < nt) STORE_STAGE(cur ^ 1);
        __syncthreads();
    }

    // ---- store C ----
    int c2 = (lane & 3) * 2;
#pragma unroll
    for (int mi = 0; mi < 4; mi++) {
        int gm0 = bm + wm * 64 + mi * 16 + r;
#pragma unroll
        for (int ni = 0; ni < 4; ni++) {
            int gn = bn + wn * 32 + ni * 8 + c2;
            float* cp0 = C + (long)gm0 * p.ldc + gn;
            float* cp1 = C + (long)(gm0 + 8) * p.ldc + gn;
            if (gn < p.N)     { cp0[0] = acc[mi][ni][0]; cp1[0] = acc[mi][ni][2]; }
            if (gn + 1 < p.N) { cp0[1] = acc[mi][ni][1]; cp1[1] = acc[mi][ni][3]; }
        }
    }
#undef LOAD_STAGE
#undef STORE_STAGE
}

// ---------------- RoPE kernels ----------------
__global__ void rope_k_kernel(const float* __restrict__ ckr,
                              const float* __restrict__ fc,
                              const float* __restrict__ fs,
                              float* __restrict__ kcat) {
    int idx = blockIdx.x * blockDim.x + threadIdx.x;
    if (idx >= 2048 * 32) return;
    int m = idx >> 5, i = idx & 31;
    int t = m & 1023;
    float re = ckr[m * 64 + 2 * i], im = ckr[m * 64 + 2 * i + 1];
    float c = fc[t * 32 + i], s = fs[t * 32 + i];
    long o = (long)m * KCAT + 512 + 2 * i;
    kcat[o]     = re * c - im * s;
    kcat[o + 1] = re * s + im * c;
}

__global__ void rope_q_kernel(const float* __restrict__ cqr,
                              const float* __restrict__ fc,
                              const float* __restrict__ fs,
                              float* __restrict__ qcat) {
    int idx = blockIdx.x * blockDim.x + threadIdx.x;
    if (idx >= 2048 * 16 * 32) return;
    int i = idx & 31;
    int h = (idx >> 5) & 15;
    int m = idx >> 9;
    int t = m & 1023, b = m >> 10;
    float re = cqr[m * 1024 + h * 64 + 2 * i];
    float im = cqr[m * 1024 + h * 64 + 2 * i + 1];
    float c = fc[t * 32 + i], s = fs[t * 32 + i];
    long o = ((long)((b * 16 + h) * 1024 + t)) * KCAT + 512 + 2 * i;
    qcat[o]     = re * c - im * s;
    qcat[o + 1] = re * s + im * c;
}

// ---------------- causal softmax (in-place, 2-pass with reg cache) -------
__global__ void softmax_causal(float* __restrict__ attn) {
    int t = blockIdx.x;
    int z = blockIdx.y;
    float* p = attn + (long)z * 1024 * 1024 + (long)t * 1024;
    int n = t + 1;
    const float scale = 0.07216878364870322992f * 1.44269504088896341f; // /sqrt(192) * log2e
    __shared__ float red[256];
    int tid = threadIdx.x;

    float vals[4];
    float m = -3.4e38f;
#pragma unroll
    for (int j = 0; j < 4; j++) {
        int s = tid + j * 256;
        vals[j] = (s < n) ? p[s] * scale : -3.4e38f;
        m = fmaxf(m, vals[j]);
    }
    red[tid] = m; __syncthreads();
    for (int o = 128; o > 0; o >>= 1) {
        if (tid < o) red[tid] = fmaxf(red[tid], red[tid + o]);
        __syncthreads();
    }
    m = red[0]; __syncthreads();

    float sum = 0.f;
#pragma unroll
    for (int j = 0; j < 4; j++) {
        int s = tid + j * 256;
        vals[j] = (s < n) ? exp2f(vals[j] - m) : 0.f;
        sum += vals[j];
    }
    red[tid] = sum; __syncthreads();
    for (int o = 128; o > 0; o >>= 1) {
        if (tid < o) red[tid] += red[tid + o];
        __syncthreads();
    }
    float inv = 1.f / red[0];

#pragma unroll
    for (int j = 0; j < 4; j++) {
        int s = tid + j * 256;
        p[s] = vals[j] * inv;
    }
}

// ---------------- host-side launch helper ----------------
static void launch_gemm(const float* A, const float* B, float* C,
                        int M, int N, int K,
                        long sAm, long sAk, long sBk, long sBn, long ldc,
                        int batches,
                        int aDiv, long aS1, int aMod, long aS2,
                        int bDiv, long bS1, int bMod, long bS2,
                        int cDiv, long cS1, int cMod, long cS2) {
    GP p;
    p.A = A; p.B = B; p.C = C;
    p.M = M; p.N = N; p.K = K;
    p.sAm = sAm; p.sAk = sAk; p.sBk = sBk; p.sBn = sBn; p.ldc = ldc;
    p.aDiv = aDiv; p.aMod = aMod; p.bDiv = bDiv; p.bMod = bMod;
    p.cDiv = cDiv; p.cMod = cMod;
    p.aS1 = aS1; p.aS2 = aS2; p.bS1 = bS1; p.bS2 = bS2; p.cS1 = cS1; p.cS2 = cS2;
    dim3 grid((N + 127) / 128, (M + 127) / 128, batches);
    tgemm<<<grid, 256>>>(p);
}

extern "C" void kernel_launch(void* const* d_in, const int* in_sizes, int n_in,
                              void* d_out, int out_size) {
    const float* x     = (const float*)d_in[0];
    const float* fcos  = (const float*)d_in[1];
    const float* fsin  = (const float*)d_in[2];
    const float* W_dq  = (const float*)d_in[3];
    const float* W_uq  = (const float*)d_in[4];
    const float* W_dkv = (const float*)d_in[5];
    const float* W_uk  = (const float*)d_in[6];
    const float* W_uv  = (const float*)d_in[7];
    const float* W_qr  = (const float*)d_in[8];
    const float* W_kr  = (const float*)d_in[9];
    const float* W_o   = (const float*)d_in[10];
    float* out = (float*)d_out;

    float *keff, *veff, *cq, *ckr, *cqr, *kcat, *qcat, *attn, *lat;
    cudaGetSymbolAddress((void**)&keff, g_keff);
    cudaGetSymbolAddress((void**)&veff, g_veff);
    cudaGetSymbolAddress((void**)&cq,   g_cq);
    cudaGetSymbolAddress((void**)&ckr,  g_ckr);
    cudaGetSymbolAddress((void**)&cqr,  g_cqr);
    cudaGetSymbolAddress((void**)&kcat, g_kcat);
    cudaGetSymbolAddress((void**)&qcat, g_qcat);
    cudaGetSymbolAddress((void**)&attn, g_attn);
    cudaGetSymbolAddress((void**)&lat,  g_lat);

    // 1) k_eff
    launch_gemm(W_uq, W_uk, keff, 512, 512, 128,
                2048, 1, 512, 1, 512, 16,
                1, 0, 16, 128,
                1, 0, 16, 128l * 512,
                1, 0, 16, 512l * 512);

    // 2) v_eff = W_uv^T @ W_o^T
    launch_gemm(W_uv, W_o, veff, 512, 2048, 2048,
                1, 512, 1, 2048, 2048, 1,
                1, 0, 1, 0, 1, 0, 1, 0, 1, 0, 1, 0);

    // 3) c_q
    launch_gemm(x, W_dq, cq, 2048, 512, 2048,
                2048, 1, 1, 2048, 512, 1,
                1, 0, 1, 0, 1, 0, 1, 0, 1, 0, 1, 0);

    // 4) c_kv -> k_cat cols [0,512)
    launch_gemm(x, W_dkv, kcat, 2048, 512, 2048,
                2048, 1, 1, 2048, KCAT, 1,
                1, 0, 1, 0, 1, 0, 1, 0, 1, 0, 1, 0);

    // 5) c_kr
    launch_gemm(x, W_kr, ckr, 2048, 64, 2048,
                2048, 1, 1, 2048, 64, 1,
                1, 0, 1, 0, 1, 0, 1, 0, 1, 0, 1, 0);

    // 6) c_qr
    launch_gemm(cq, W_qr, cqr, 2048, 1024, 512,
                512, 1, 1, 512, 1024, 1,
                1, 0, 1, 0, 1, 0, 1, 0, 1, 0, 1, 0);

    // 7-8) RoPE
    rope_k_kernel<<<(2048 * 32 + 255) / 256, 256>>>(ckr, fcos, fsin, kcat);
    rope_q_kernel<<<(2048 * 16 * 32 + 255) / 256, 256>>>(cqr, fcos, fsin, qcat);

    // 9) q_abs
    launch_gemm(cq, keff, qcat, 1024, 512, 512,
                512, 1, 512, 1, KCAT, 32,
                16, 1024l * 512, 1, 0,
                1, 0, 16, 512l * 512,
                1, 0, 32, 1024l * KCAT);

    // 10) logits (K=576 fused)
    launch_gemm(qcat, kcat, attn, 1024, 1024, KCAT,
                KCAT, 1, 1, KCAT, 1024, 32,
                1, 0, 32, 1024l * KCAT,
                16, 1024l * KCAT, 1, 0,
                1, 0, 32, 1024l * 1024);

    // 11) softmax
    {
        dim3 grid(1024, 32);
        softmax_causal<<<grid, 256>>>(attn);
    }

    // 12) lat
    launch_gemm(attn, kcat, lat, 1024, 512, 1024,
                1024, 1, KCAT, 1, 512, 32,
                1, 0, 32, 1024l * 1024,
                16, 1024l * KCAT, 1, 0,
                1, 0, 32, 1024l * 512);

    // 13) y
    launch_gemm(lat, veff, out, 1024, 128, 512,
                512, 1, 2048, 1, 2048, 32,
                1, 0, 32, 1024l * 512,
                1, 0, 16, 128,
                16, 1024l * 2048, 16, 128);
}

// round 4
// speedup vs baseline: 3.2323x; 2.0367x over previous
#include <cuda_runtime.h>
#include <cuda_bf16.h>
#include <math.h>

#define BB   2
#define TT   1024
#define CC   2048
#define NH   16
#define HS   128
#define NLQ  512
#define NLKV 512
#define DHR  64
#define KCAT 576

// ---------------- scratch ----------------
__device__ float g_keff[16l * 512 * 512];
__device__ float g_veff[512l * 2048];
__device__ float g_cq  [2048l * 512];
__device__ float g_ckr [2048l * 64];
__device__ float g_cqr [2048l * 1024];
__device__ float g_kcat[2048l * 576];
__device__ float g_qcat[32l * 1024 * 576];
__device__ float g_attn[32l * 1024 * 1024];
__device__ float g_lat [32l * 1024 * 512];

struct GP {
    const float* A; const float* B; float* C;
    int M, N, K;
    long sAm, sAk, sBk, sBn, ldc;
    int aDiv, aMod, bDiv, bMod, cDiv, cMod;
    long aS1, aS2, bS1, bS2, cS1, cS2;
    int kSplit;      // grid.z = batches * kSplit; atomicAdd epilogue if >1
};

__device__ __forceinline__ unsigned f2tf32(float x) {
    unsigned u;
    asm("cvt.rna.tf32.f32 %0, %1;" : "=r"(u) : "f"(x));
    return u;
}

__device__ __forceinline__ void mma_tf32(float* d, const unsigned* a,
                                         const unsigned* b) {
    asm volatile(
        "mma.sync.aligned.m16n8k8.row.col.f32.tf32.tf32.f32 "
        "{%0,%1,%2,%3}, {%4,%5,%6,%7}, {%8,%9}, {%0,%1,%2,%3};\n"
        : "+f"(d[0]), "+f"(d[1]), "+f"(d[2]), "+f"(d[3])
        : "r"(a[0]), "r"(a[1]), "r"(a[2]), "r"(a[3]),
          "r"(b[0]), "r"(b[1]));
}

#define SPAD 136   // %32==8 -> conflict-free fragment reads

// TF32 GEMM: block 128x128, k-tile 8, 4 warps (2x2), warp tile 64x64,
// double-buffered smem, register-staged prefetch, optional split-K.
__global__ __launch_bounds__(128) void tgemm(GP p) {
    int z = blockIdx.z;
    int zb = z / p.kSplit;            // batch index
    int kz = z % p.kSplit;            // k-slice index
    int kLen = p.K / p.kSplit;        // guaranteed divisible by 8

    const float* A = p.A + (long)(zb / p.aDiv) * p.aS1 + (long)(zb % p.aMod) * p.aS2
                   + (long)kz * kLen * p.sAk;
    const float* B = p.B + (long)(zb / p.bDiv) * p.bS1 + (long)(zb % p.bMod) * p.bS2
                   + (long)kz * kLen * p.sBk;
    float*       C = p.C + (long)(zb / p.cDiv) * p.cS1 + (long)(zb % p.cMod) * p.cS2;

    __shared__ unsigned As[2][8][SPAD];
    __shared__ unsigned Bs[2][8][SPAD];

    int tid  = threadIdx.x;
    int lane = tid & 31;
    int wid  = tid >> 5;
    int wm = wid >> 1;          // 0..1
    int wn = wid & 1;           // 0..1
    int bm = blockIdx.y * 128, bn = blockIdx.x * 128;

    const bool aKc = (p.sAk == 1);
    const bool bKc = (p.sBk == 1);

    // staging indices
    int a_i0, a_i1;  const float* aBase;  long aStep;
    if (aKc) {
        a_i1 = tid;                   // m (0..127)
        a_i0 = 0;
        aBase = A + (long)(bm + a_i1) * p.sAm;
        aStep = 8;
    } else {
        a_i0 = tid >> 4;              // k (0..7)
        a_i1 = (tid & 15) * 8;        // m start
        aBase = A + (long)a_i0 * p.sAk + (bm + a_i1);
        aStep = 8 * p.sAk;
    }
    int b_i0, b_i1;  const float* bBase;  long bStep;  bool bOk;
    if (bKc) {
        b_i1 = tid;                   // n
        b_i0 = 0;
        bOk = (bn + b_i1) < p.N;
        bBase = B + (long)(bn + b_i1) * p.sBn;
        bStep = 8;
    } else {
        b_i0 = tid >> 4;              // k
        b_i1 = (tid & 15) * 8;        // n start
        bOk = (bn + b_i1) < p.N;
        bBase = B + (long)b_i0 * p.sBk + (bn + b_i1);
        bStep = 8 * p.sBk;
    }

    float ra[8], rb[8];

#define LOAD_STAGE(t)                                                        \
    {                                                                        \
        const float* ap = aBase + (long)(t) * aStep;                         \
        float4 v0 = *(const float4*)ap;                                      \
        float4 v1 = *(const float4*)(ap + 4);                                \
        ra[0]=v0.x; ra[1]=v0.y; ra[2]=v0.z; ra[3]=v0.w;                      \
        ra[4]=v1.x; ra[5]=v1.y; ra[6]=v1.z; ra[7]=v1.w;                      \
        if (bOk) {                                                           \
            const float* bp = bBase + (long)(t) * bStep;                     \
            float4 w0 = *(const float4*)bp;                                  \
            float4 w1 = *(const float4*)(bp + 4);                            \
            rb[0]=w0.x; rb[1]=w0.y; rb[2]=w0.z; rb[3]=w0.w;                  \
            rb[4]=w1.x; rb[5]=w1.y; rb[6]=w1.z; rb[7]=w1.w;                  \
        } else {                                                             \
            rb[0]=rb[1]=rb[2]=rb[3]=rb[4]=rb[5]=rb[6]=rb[7]=0.f;             \
        }                                                                    \
    }

#define STORE_STAGE(buf)                                                     \
    {                                                                        \
        if (aKc) {                                                           \
            _Pragma("unroll")                                                \
            for (int j = 0; j < 8; j++) As[buf][j][a_i1] = f2tf32(ra[j]);    \
        } else {                                                             \
            _Pragma("unroll")                                                \
            for (int j = 0; j < 8; j++) As[buf][a_i0][a_i1 + j] = f2tf32(ra[j]); \
        }                                                                    \
        if (bKc) {                                                           \
            _Pragma("unroll")                                                \
            for (int j = 0; j < 8; j++) Bs[buf][j][b_i1] = f2tf32(rb[j]);    \
        } else {                                                             \
            _Pragma("unroll")                                                \
            for (int j = 0; j < 8; j++) Bs[buf][b_i0][b_i1 + j] = f2tf32(rb[j]); \
        }                                                                    \
    }

    float acc[4][8][4];
#pragma unroll
    for (int i = 0; i < 4; i++)
#pragma unroll
        for (int j = 0; j < 8; j++)
#pragma unroll
            for (int r = 0; r < 4; r++) acc[i][j][r] = 0.f;

    int nt = kLen >> 3;

    LOAD_STAGE(0);
    STORE_STAGE(0);
    __syncthreads();

    int r = lane >> 2, c = lane & 3;

    for (int t = 0; t < nt; t++) {
        int cur = t & 1;
        if (t + 1 < nt) LOAD_STAGE(t + 1);

        unsigned a[4][4], b[8][2];
#pragma unroll
        for (int mi = 0; mi < 4; mi++) {
            int m = wm * 64 + mi * 16 + r;
            a[mi][0] = As[cur][c][m];
            a[mi][1] = As[cur][c][m + 8];
            a[mi][2] = As[cur][c + 4][m];
            a[mi][3] = As[cur][c + 4][m + 8];
        }
#pragma unroll
        for (int ni = 0; ni < 8; ni++) {
            int n = wn * 64 + ni * 8 + r;
            b[ni][0] = Bs[cur][c][n];
            b[ni][1] = Bs[cur][c + 4][n];
        }
#pragma unroll
        for (int mi = 0; mi < 4; mi++)
#pragma unroll
            for (int ni = 0; ni < 8; ni++)
                mma_tf32(acc[mi][ni], a[mi], b[ni]);

        if (t + 1 < nt) STORE_STAGE(cur ^ 1);
        __syncthreads();
    }

    // ---- epilogue ----
    int c2 = (lane & 3) * 2;
    if (p.kSplit > 1) {
#pragma unroll
        for (int mi = 0; mi < 4; mi++) {
            int gm0 = bm + wm * 64 + mi * 16 + r;
#pragma unroll
            for (int ni = 0; ni < 8; ni++) {
                int gn = bn + wn * 64 + ni * 8 + c2;
                if (gn < p.N) {
                    atomicAdd(C + (long)gm0 * p.ldc + gn,     acc[mi][ni][0]);
                    atomicAdd(C + (long)gm0 * p.ldc + gn + 1, acc[mi][ni][1]);
                    atomicAdd(C + (long)(gm0 + 8) * p.ldc + gn,     acc[mi][ni][2]);
                    atomicAdd(C + (long)(gm0 + 8) * p.ldc + gn + 1, acc[mi][ni][3]);
                }
            }
        }
    } else {
#pragma unroll
        for (int mi = 0; mi < 4; mi++) {
            int gm0 = bm + wm * 64 + mi * 16 + r;
#pragma unroll
            for (int ni = 0; ni < 8; ni++) {
                int gn = bn + wn * 64 + ni * 8 + c2;
                if (gn < p.N) {
                    float* cp0 = C + (long)gm0 * p.ldc + gn;
                    float* cp1 = C + (long)(gm0 + 8) * p.ldc + gn;
                    cp0[0] = acc[mi][ni][0]; cp0[1] = acc[mi][ni][1];
                    cp1[0] = acc[mi][ni][2]; cp1[1] = acc[mi][ni][3];
                }
            }
        }
    }
#undef LOAD_STAGE
#undef STORE_STAGE
}

// ---------------- RoPE ----------------
__global__ void rope_k_kernel(const float* __restrict__ ckr,
                              const float* __restrict__ fc,
                              const float* __restrict__ fs,
                              float* __restrict__ kcat) {
    int idx = blockIdx.x * blockDim.x + threadIdx.x;
    if (idx >= 2048 * 32) return;
    int m = idx >> 5, i = idx & 31;
    int t = m & 1023;
    float re = ckr[m * 64 + 2 * i], im = ckr[m * 64 + 2 * i + 1];
    float c = fc[t * 32 + i], s = fs[t * 32 + i];
    long o = (long)m * KCAT + 512 + 2 * i;
    kcat[o]     = re * c - im * s;
    kcat[o + 1] = re * s + im * c;
}

__global__ void rope_q_kernel(const float* __restrict__ cqr,
                              const float* __restrict__ fc,
                              const float* __restrict__ fs,
                              float* __restrict__ qcat) {
    int idx = blockIdx.x * blockDim.x + threadIdx.x;
    if (idx >= 2048 * 16 * 32) return;
    int i = idx & 31;
    int h = (idx >> 5) & 15;
    int m = idx >> 9;
    int t = m & 1023, b = m >> 10;
    float re = cqr[m * 1024 + h * 64 + 2 * i];
    float im = cqr[m * 1024 + h * 64 + 2 * i + 1];
    float c = fc[t * 32 + i], s = fs[t * 32 + i];
    long o = ((long)((b * 16 + h) * 1024 + t)) * KCAT + 512 + 2 * i;
    qcat[o]     = re * c - im * s;
    qcat[o + 1] = re * s + im * c;
}

// ---------------- causal softmax ----------------
__global__ void softmax_causal(float* __restrict__ attn) {
    int t = blockIdx.x;
    int z = blockIdx.y;
    float* p = attn + (long)z * 1024 * 1024 + (long)t * 1024;
    int n = t + 1;
    const float scale = 0.07216878364870322992f * 1.44269504088896341f;
    __shared__ float red[256];
    int tid = threadIdx.x;

    float vals[4];
    float m = -3.4e38f;
#pragma unroll
    for (int j = 0; j < 4; j++) {
        int s = tid + j * 256;
        vals[j] = (s < n) ? p[s] * scale : -3.4e38f;
        m = fmaxf(m, vals[j]);
    }
    red[tid] = m; __syncthreads();
    for (int o = 128; o > 0; o >>= 1) {
        if (tid < o) red[tid] = fmaxf(red[tid], red[tid + o]);
        __syncthreads();
    }
    m = red[0]; __syncthreads();

    float sum = 0.f;
#pragma unroll
    for (int j = 0; j < 4; j++) {
        int s = tid + j * 256;
        vals[j] = (s < n) ? exp2f(vals[j] - m) : 0.f;
        sum += vals[j];
    }
    red[tid] = sum; __syncthreads();
    for (int o = 128; o > 0; o >>= 1) {
        if (tid < o) red[tid] += red[tid + o];
        __syncthreads();
    }
    float inv = 1.f / red[0];

#pragma unroll
    for (int j = 0; j < 4; j++) {
        int s = tid + j * 256;
        p[s] = vals[j] * inv;
    }
}

// ---------------- launch helper ----------------
static void launch_gemm(const float* A, const float* B, float* C,
                        int M, int N, int K,
                        long sAm, long sAk, long sBk, long sBn, long ldc,
                        int batches,
                        int aDiv, long aS1, int aMod, long aS2,
                        int bDiv, long bS1, int bMod, long bS2,
                        int cDiv, long cS1, int cMod, long cS2,
                        int kSplit = 1) {
    GP p;
    p.A = A; p.B = B; p.C = C;
    p.M = M; p.N = N; p.K = K;
    p.sAm = sAm; p.sAk = sAk; p.sBk = sBk; p.sBn = sBn; p.ldc = ldc;
    p.aDiv = aDiv; p.aMod = aMod; p.bDiv = bDiv; p.bMod = bMod;
    p.cDiv = cDiv; p.cMod = cMod;
    p.aS1 = aS1; p.aS2 = aS2; p.bS1 = bS1; p.bS2 = bS2; p.cS1 = cS1; p.cS2 = cS2;
    p.kSplit = kSplit;
    dim3 grid((N + 127) / 128, (M + 127) / 128, batches * kSplit);
    tgemm<<<grid, 128>>>(p);
}

extern "C" void kernel_launch(void* const* d_in, const int* in_sizes, int n_in,
                              void* d_out, int out_size) {
    const float* x     = (const float*)d_in[0];
    const float* fcos  = (const float*)d_in[1];
    const float* fsin  = (const float*)d_in[2];
    const float* W_dq  = (const float*)d_in[3];
    const float* W_uq  = (const float*)d_in[4];
    const float* W_dkv = (const float*)d_in[5];
    const float* W_uk  = (const float*)d_in[6];
    const float* W_uv  = (const float*)d_in[7];
    const float* W_qr  = (const float*)d_in[8];
    const float* W_kr  = (const float*)d_in[9];
    const float* W_o   = (const float*)d_in[10];
    float* out = (float*)d_out;

    float *keff, *veff, *cq, *ckr, *cqr, *kcat, *qcat, *attn, *lat;
    cudaGetSymbolAddress((void**)&keff, g_keff);
    cudaGetSymbolAddress((void**)&veff, g_veff);
    cudaGetSymbolAddress((void**)&cq,   g_cq);
    cudaGetSymbolAddress((void**)&ckr,  g_ckr);
    cudaGetSymbolAddress((void**)&cqr,  g_cqr);
    cudaGetSymbolAddress((void**)&kcat, g_kcat);
    cudaGetSymbolAddress((void**)&qcat, g_qcat);
    cudaGetSymbolAddress((void**)&attn, g_attn);
    cudaGetSymbolAddress((void**)&lat,  g_lat);

    // zero split-K accumulation targets
    cudaMemsetAsync(veff, 0, 512l * 2048 * 4);
    cudaMemsetAsync(cq,   0, 2048l * 512 * 4);
    cudaMemsetAsync(ckr,  0, 2048l * 64 * 4);
    cudaMemsetAsync(cqr,  0, 2048l * 1024 * 4);
    cudaMemsetAsync(kcat, 0, 2048l * 576 * 4);

    // 1) k_eff   grid (4,4,16)=256
    launch_gemm(W_uq, W_uk, keff, 512, 512, 128,
                2048, 1, 512, 1, 512, 16,
                1, 0, 16, 128,
                1, 0, 16, 128l * 512,
                1, 0, 16, 512l * 512);

    // 2) v_eff  (split-K 4 -> grid 256)
    launch_gemm(W_uv, W_o, veff, 512, 2048, 2048,
                1, 512, 1, 2048, 2048, 1,
                1, 0, 1, 0, 1, 0, 1, 0, 1, 0, 1, 0, 4);

    // 3) c_q  (split-K 4 -> grid 256)
    launch_gemm(x, W_dq, cq, 2048, 512, 2048,
                2048, 1, 1, 2048, 512, 1,
                1, 0, 1, 0, 1, 0, 1, 0, 1, 0, 1, 0, 4);

    // 4) c_kv -> k_cat cols [0,512)  (split-K 4)
    launch_gemm(x, W_dkv, kcat, 2048, 512, 2048,
                2048, 1, 1, 2048, KCAT, 1,
                1, 0, 1, 0, 1, 0, 1, 0, 1, 0, 1, 0, 4);

    // 5) c_kr  (split-K 8 -> grid 128)
    launch_gemm(x, W_kr, ckr, 2048, 64, 2048,
                2048, 1, 1, 2048, 64, 1,
                1, 0, 1, 0, 1, 0, 1, 0, 1, 0, 1, 0, 8);

    // 6) c_qr  (split-K 2 -> grid 256)
    launch_gemm(cq, W_qr, cqr, 2048, 1024, 512,
                512, 1, 1, 512, 1024, 1,
                1, 0, 1, 0, 1, 0, 1, 0, 1, 0, 1, 0, 2);

    // 7-8) RoPE
    rope_k_kernel<<<(2048 * 32 + 255) / 256, 256>>>(ckr, fcos, fsin, kcat);
    rope_q_kernel<<<(2048 * 16 * 32 + 255) / 256, 256>>>(cqr, fcos, fsin, qcat);

    // 9) q_abs  grid (4,8,32)=1024
    launch_gemm(cq, keff, qcat, 1024, 512, 512,
                512, 1, 512, 1, KCAT, 32,
                16, 1024l * 512, 1, 0,
                1, 0, 16, 512l * 512,
                1, 0, 32, 1024l * KCAT);

    // 10) logits  grid (8,8,32)=2048
    launch_gemm(qcat, kcat, attn, 1024, 1024, KCAT,
                KCAT, 1, 1, KCAT, 1024, 32,
                1, 0, 32, 1024l * KCAT,
                16, 1024l * KCAT, 1, 0,
                1, 0, 32, 1024l * 1024);

    // 11) softmax
    {
        dim3 grid(1024, 32);
        softmax_causal<<<grid, 256>>>(attn);
    }

    // 12) lat  grid (4,8,32)=1024
    launch_gemm(attn, kcat, lat, 1024, 512, 1024,
                1024, 1, KCAT, 1, 512, 32,
                1, 0, 32, 1024l * 1024,
                16, 1024l * KCAT, 1, 0,
                1, 0, 32, 1024l * 512);

    // 13) y  grid (1,8,32)=256
    launch_gemm(lat, veff, out, 1024, 128, 512,
                512, 1, 2048, 1, 2048, 32,
                1, 0, 32, 1024l * 512,
                1, 0, 16, 128,
                16, 1024l * 2048, 16, 128);
}

// round 6
// speedup vs baseline: 4.2168x; 1.3046x over previous
#include <cuda_runtime.h>
#include <cuda_bf16.h>
#include <math.h>

#define BB   2
#define TT   1024
#define CC   2048
#define NH   16
#define HS   128
#define NLQ  512
#define NLKV 512
#define DHR  64
#define KCAT 576

// ---------------- scratch ----------------
__device__ float g_keff[16l * 512 * 512];
__device__ float g_veff[2048l * 512];           // veff_t[j][k] (k contiguous)
__device__ float g_cq  [2048l * 512];
__device__ float g_ckr [2048l * 64];
__device__ float g_cqr [2048l * 1024];
__device__ float g_kcat[2048l * 576];
__device__ float g_qcat[32l * 1024 * 576];
__device__ float g_attn[32l * 1024 * 1024];
__device__ float g_lat [32l * 1024 * 512];

struct GP {
    const float* A; const float* B; float* C;
    int M, N, K;
    long sAm, sAk, sBk, sBn, ldc;
    int aDiv, aMod, bDiv, bMod, cDiv, cMod;
    long aS1, aS2, bS1, bS2, cS1, cS2;
    int kSplit;
    int mode;    // 0 plain, 1 causal tile-skip, 2 causal k-stop
};

__device__ __forceinline__ unsigned f2tf32(float x) {
    unsigned u;
    asm("cvt.rna.tf32.f32 %0, %1;" : "=r"(u) : "f"(x));
    return u;
}

__device__ __forceinline__ void mma_tf32(float* d, const unsigned* a,
                                         const unsigned* b) {
    asm volatile(
        "mma.sync.aligned.m16n8k8.row.col.f32.tf32.tf32.f32 "
        "{%0,%1,%2,%3}, {%4,%5,%6,%7}, {%8,%9}, {%0,%1,%2,%3};\n"
        : "+f"(d[0]), "+f"(d[1]), "+f"(d[2]), "+f"(d[3])
        : "r"(a[0]), "r"(a[1]), "r"(a[2]), "r"(a[3]),
          "r"(b[0]), "r"(b[1]));
}

#define SPAD 136

// TF32 GEMM: block 128x128, k-tile 8, 4 warps (2x2), warp tile 64x64,
// double-buffered smem, register-staged prefetch, split-K + causal modes.
__global__ __launch_bounds__(128) void tgemm(GP p) {
    int bmI = blockIdx.y, bnI = blockIdx.x;
    if (p.mode == 1 && bnI > bmI) return;

    int z = blockIdx.z;
    int zb = z / p.kSplit;
    int kz = z % p.kSplit;

    int kTot = p.K;
    if (p.mode == 2) { int ke = (bmI + 1) * 128; if (ke < kTot) kTot = ke; }
    int kLen = kTot / p.kSplit;

    const float* A = p.A + (long)(zb / p.aDiv) * p.aS1 + (long)(zb % p.aMod) * p.aS2
                   + (long)kz * kLen * p.sAk;
    const float* B = p.B + (long)(zb / p.bDiv) * p.bS1 + (long)(zb % p.bMod) * p.bS2
                   + (long)kz * kLen * p.sBk;
    float*       C = p.C + (long)(zb / p.cDiv) * p.cS1 + (long)(zb % p.cMod) * p.cS2;

    __shared__ unsigned As[2][8][SPAD];
    __shared__ unsigned Bs[2][8][SPAD];

    int tid  = threadIdx.x;
    int lane = tid & 31;
    int wid  = tid >> 5;
    int wm = wid >> 1, wn = wid & 1;
    int bm = bmI * 128, bn = bnI * 128;

    const bool aKc = (p.sAk == 1);
    const bool bKc = (p.sBk == 1);

    int a_i0, a_i1;  const float* aBase;  long aStep;
    if (aKc) {
        a_i1 = tid; a_i0 = 0;
        aBase = A + (long)(bm + a_i1) * p.sAm;
        aStep = 8;
    } else {
        a_i0 = tid >> 4; a_i1 = (tid & 15) * 8;
        aBase = A + (long)a_i0 * p.sAk + (bm + a_i1);
        aStep = 8 * p.sAk;
    }
    int b_i0, b_i1;  const float* bBase;  long bStep;  bool bOk;
    if (bKc) {
        b_i1 = tid; b_i0 = 0;
        bOk = (bn + b_i1) < p.N;
        bBase = B + (long)(bn + b_i1) * p.sBn;
        bStep = 8;
    } else {
        b_i0 = tid >> 4; b_i1 = (tid & 15) * 8;
        bOk = (bn + b_i1) < p.N;
        bBase = B + (long)b_i0 * p.sBk + (bn + b_i1);
        bStep = 8 * p.sBk;
    }

    float ra[8], rb[8];

#define LOAD_STAGE(t)                                                        \
    {                                                                        \
        const float* ap = aBase + (long)(t) * aStep;                         \
        float4 v0 = *(const float4*)ap;                                      \
        float4 v1 = *(const float4*)(ap + 4);                                \
        ra[0]=v0.x; ra[1]=v0.y; ra[2]=v0.z; ra[3]=v0.w;                      \
        ra[4]=v1.x; ra[5]=v1.y; ra[6]=v1.z; ra[7]=v1.w;                      \
        if (bOk) {                                                           \
            const float* bp = bBase + (long)(t) * bStep;                     \
            float4 w0 = *(const float4*)bp;                                  \
            float4 w1 = *(const float4*)(bp + 4);                            \
            rb[0]=w0.x; rb[1]=w0.y; rb[2]=w0.z; rb[3]=w0.w;                  \
            rb[4]=w1.x; rb[5]=w1.y; rb[6]=w1.z; rb[7]=w1.w;                  \
        } else {                                                             \
            rb[0]=rb[1]=rb[2]=rb[3]=rb[4]=rb[5]=rb[6]=rb[7]=0.f;             \
        }                                                                    \
    }

#define STORE_STAGE(buf)                                                     \
    {                                                                        \
        if (aKc) {                                                           \
            _Pragma("unroll")                                                \
            for (int j = 0; j < 8; j++) As[buf][j][a_i1] = f2tf32(ra[j]);    \
        } else {                                                             \
            _Pragma("unroll")                                                \
            for (int j = 0; j < 8; j++) As[buf][a_i0][a_i1 + j] = f2tf32(ra[j]); \
        }                                                                    \
        if (bKc) {                                                           \
            _Pragma("unroll")                                                \
            for (int j = 0; j < 8; j++) Bs[buf][j][b_i1] = f2tf32(rb[j]);    \
        } else {                                                             \
            _Pragma("unroll")                                                \
            for (int j = 0; j < 8; j++) Bs[buf][b_i0][b_i1 + j] = f2tf32(rb[j]); \
        }                                                                    \
    }

    float acc[4][8][4];
#pragma unroll
    for (int i = 0; i < 4; i++)
#pragma unroll
        for (int j = 0; j < 8; j++)
#pragma unroll
            for (int r = 0; r < 4; r++) acc[i][j][r] = 0.f;

    int nt = kLen >> 3;

    LOAD_STAGE(0);
    STORE_STAGE(0);
    __syncthreads();

    int r = lane >> 2, c = lane & 3;

    for (int t = 0; t < nt; t++) {
        int cur = t & 1;
        if (t + 1 < nt) LOAD_STAGE(t + 1);

        unsigned a[4][4], b[8][2];
#pragma unroll
        for (int mi = 0; mi < 4; mi++) {
            int m = wm * 64 + mi * 16 + r;
            a[mi][0] = As[cur][c][m];
            a[mi][1] = As[cur][c][m + 8];
            a[mi][2] = As[cur][c + 4][m];
            a[mi][3] = As[cur][c + 4][m + 8];
        }
#pragma unroll
        for (int ni = 0; ni < 8; ni++) {
            int n = wn * 64 + ni * 8 + r;
            b[ni][0] = Bs[cur][c][n];
            b[ni][1] = Bs[cur][c + 4][n];
        }
#pragma unroll
        for (int mi = 0; mi < 4; mi++)
#pragma unroll
            for (int ni = 0; ni < 8; ni++)
                mma_tf32(acc[mi][ni], a[mi], b[ni]);

        if (t + 1 < nt) STORE_STAGE(cur ^ 1);
        __syncthreads();
    }

    int c2 = (lane & 3) * 2;
    if (p.kSplit > 1) {
#pragma unroll
        for (int mi = 0; mi < 4; mi++) {
            int gm0 = bm + wm * 64 + mi * 16 + r;
#pragma unroll
            for (int ni = 0; ni < 8; ni++) {
                int gn = bn + wn * 64 + ni * 8 + c2;
                if (gn < p.N) {
                    atomicAdd(C + (long)gm0 * p.ldc + gn,     acc[mi][ni][0]);
                    atomicAdd(C + (long)gm0 * p.ldc + gn + 1, acc[mi][ni][1]);
                    atomicAdd(C + (long)(gm0 + 8) * p.ldc + gn,     acc[mi][ni][2]);
                    atomicAdd(C + (long)(gm0 + 8) * p.ldc + gn + 1, acc[mi][ni][3]);
                }
            }
        }
    } else {
#pragma unroll
        for (int mi = 0; mi < 4; mi++) {
            int gm0 = bm + wm * 64 + mi * 16 + r;
#pragma unroll
            for (int ni = 0; ni < 8; ni++) {
                int gn = bn + wn * 64 + ni * 8 + c2;
                if (gn < p.N) {
                    float* cp0 = C + (long)gm0 * p.ldc + gn;
                    float* cp1 = C + (long)(gm0 + 8) * p.ldc + gn;
                    cp0[0] = acc[mi][ni][0]; cp0[1] = acc[mi][ni][1];
                    cp1[0] = acc[mi][ni][2]; cp1[1] = acc[mi][ni][3];
                }
            }
        }
    }
#undef LOAD_STAGE
#undef STORE_STAGE
}

// ---------------- RoPE ----------------
__global__ void rope_k_kernel(const float* __restrict__ ckr,
                              const float* __restrict__ fc,
                              const float* __restrict__ fs,
                              float* __restrict__ kcat) {
    int idx = blockIdx.x * blockDim.x + threadIdx.x;
    if (idx >= 2048 * 32) return;
    int m = idx >> 5, i = idx & 31;
    int t = m & 1023;
    float re = ckr[m * 64 + 2 * i], im = ckr[m * 64 + 2 * i + 1];
    float c = fc[t * 32 + i], s = fs[t * 32 + i];
    long o = (long)m * KCAT + 512 + 2 * i;
    kcat[o]     = re * c - im * s;
    kcat[o + 1] = re * s + im * c;
}

__global__ void rope_q_kernel(const float* __restrict__ cqr,
                              const float* __restrict__ fc,
                              const float* __restrict__ fs,
                              float* __restrict__ qcat) {
    int idx = blockIdx.x * blockDim.x + threadIdx.x;
    if (idx >= 2048 * 16 * 32) return;
    int i = idx & 31;
    int h = (idx >> 5) & 15;
    int m = idx >> 9;
    int t = m & 1023, b = m >> 10;
    float re = cqr[m * 1024 + h * 64 + 2 * i];
    float im = cqr[m * 1024 + h * 64 + 2 * i + 1];
    float c = fc[t * 32 + i], s = fs[t * 32 + i];
    long o = ((long)((b * 16 + h) * 1024 + t)) * KCAT + 512 + 2 * i;
    qcat[o]     = re * c - im * s;
    qcat[o + 1] = re * s + im * c;
}

// ---------------- causal softmax (writes only up to block boundary) ------
__global__ void softmax_causal(float* __restrict__ attn) {
    int t = blockIdx.x;
    int z = blockIdx.y;
    float* p = attn + (long)z * 1024 * 1024 + (long)t * 1024;
    int n = t + 1;
    int lim = ((t >> 7) + 1) << 7;
    const float scale = 0.07216878364870322992f * 1.44269504088896341f;
    __shared__ float red[256];
    int tid = threadIdx.x;

    float vals[4];
    float m = -3.4e38f;
#pragma unroll
    for (int j = 0; j < 4; j++) {
        int s = tid + j * 256;
        vals[j] = (s < n) ? p[s] * scale : -3.4e38f;
        m = fmaxf(m, vals[j]);
    }
    red[tid] = m; __syncthreads();
    for (int o = 128; o > 0; o >>= 1) {
        if (tid < o) red[tid] = fmaxf(red[tid], red[tid + o]);
        __syncthreads();
    }
    m = red[0]; __syncthreads();

    float sum = 0.f;
#pragma unroll
    for (int j = 0; j < 4; j++) {
        int s = tid + j * 256;
        vals[j] = (s < n) ? exp2f(vals[j] - m) : 0.f;
        sum += vals[j];
    }
    red[tid] = sum; __syncthreads();
    for (int o = 128; o > 0; o >>= 1) {
        if (tid < o) red[tid] += red[tid + o];
        __syncthreads();
    }
    float inv = 1.f / red[0];

#pragma unroll
    for (int j = 0; j < 4; j++) {
        int s = tid + j * 256;
        if (s < lim) p[s] = vals[j] * inv;
    }
}

// ---------------- launch helper ----------------
static void launch_gemm(const float* A, const float* B, float* C,
                        int M, int N, int K,
                        long sAm, long sAk, long sBk, long sBn, long ldc,
                        int batches,
                        int aDiv, long aS1, int aMod, long aS2,
                        int bDiv, long bS1, int bMod, long bS2,
                        int cDiv, long cS1, int cMod, long cS2,
                        int kSplit = 1, int mode = 0) {
    GP p;
    p.A = A; p.B = B; p.C = C;
    p.M = M; p.N = N; p.K = K;
    p.sAm = sAm; p.sAk = sAk; p.sBk = sBk; p.sBn = sBn; p.ldc = ldc;
    p.aDiv = aDiv; p.aMod = aMod; p.bDiv = bDiv; p.bMod = bMod;
    p.cDiv = cDiv; p.cMod = cMod;
    p.aS1 = aS1; p.aS2 = aS2; p.bS1 = bS1; p.bS2 = bS2; p.cS1 = cS1; p.cS2 = cS2;
    p.kSplit = kSplit; p.mode = mode;
    dim3 grid((N + 127) / 128, (M + 127) / 128, batches * kSplit);
    tgemm<<<grid, 128>>>(p);
}

extern "C" void kernel_launch(void* const* d_in, const int* in_sizes, int n_in,
                              void* d_out, int out_size) {
    const float* x     = (const float*)d_in[0];
    const float* fcos  = (const float*)d_in[1];
    const float* fsin  = (const float*)d_in[2];
    const float* W_dq  = (const float*)d_in[3];
    const float* W_uq  = (const float*)d_in[4];
    const float* W_dkv = (const float*)d_in[5];
    const float* W_uk  = (const float*)d_in[6];
    const float* W_uv  = (const float*)d_in[7];
    const float* W_qr  = (const float*)d_in[8];
    const float* W_kr  = (const float*)d_in[9];
    const float* W_o   = (const float*)d_in[10];
    float* out = (float*)d_out;

    float *keff, *veff, *cq, *ckr, *cqr, *kcat, *qcat, *attn, *lat;
    cudaGetSymbolAddress((void**)&keff, g_keff);
    cudaGetSymbolAddress((void**)&veff, g_veff);
    cudaGetSymbolAddress((void**)&cq,   g_cq);
    cudaGetSymbolAddress((void**)&ckr,  g_ckr);
    cudaGetSymbolAddress((void**)&cqr,  g_cqr);
    cudaGetSymbolAddress((void**)&kcat, g_kcat);
    cudaGetSymbolAddress((void**)&qcat, g_qcat);
    cudaGetSymbolAddress((void**)&attn, g_attn);
    cudaGetSymbolAddress((void**)&lat,  g_lat);

    cudaMemsetAsync(veff, 0, 2048l * 512 * 4);
    cudaMemsetAsync(cq,   0, 2048l * 512 * 4);
    cudaMemsetAsync(ckr,  0, 2048l * 64 * 4);
    cudaMemsetAsync(cqr,  0, 2048l * 1024 * 4);
    cudaMemsetAsync(kcat, 0, 2048l * 576 * 4);

    // 1) k_eff[h][q][k]
    launch_gemm(W_uq, W_uk, keff, 512, 512, 128,
                2048, 1, 512, 1, 512, 16,
                1, 0, 16, 128,
                1, 0, 16, 128l * 512,
                1, 0, 16, 512l * 512);

    // 2) veff_t[j][k] = sum_c W_o[j*2048+c] * W_uv[c*512+k]   (split-K 4)
    launch_gemm(W_o, W_uv, veff, 2048, 512, 2048,
                2048, 1, 512, 1, 512, 1,
                1, 0, 1, 0, 1, 0, 1, 0, 1, 0, 1, 0, 4);

    // 3) c_q  (split-K 4)
    launch_gemm(x, W_dq, cq, 2048, 512, 2048,
                2048, 1, 1, 2048, 512, 1,
                1, 0, 1, 0, 1, 0, 1, 0, 1, 0, 1, 0, 4);

    // 4) c_kv -> kcat cols [0,512)  (split-K 4)
    launch_gemm(x, W_dkv, kcat, 2048, 512, 2048,
                2048, 1, 1, 2048, KCAT, 1,
                1, 0, 1, 0, 1, 0, 1, 0, 1, 0, 1, 0, 4);

    // 5) c_kr  (split-K 8)
    launch_gemm(x, W_kr, ckr, 2048, 64, 2048,
                2048, 1, 1, 2048, 64, 1,
                1, 0, 1, 0, 1, 0, 1, 0, 1, 0, 1, 0, 8);

    // 6) c_qr  (split-K 2)
    launch_gemm(cq, W_qr, cqr, 2048, 1024, 512,
                512, 1, 1, 512, 1024, 1,
                1, 0, 1, 0, 1, 0, 1, 0, 1, 0, 1, 0, 2);

    // 7-8) RoPE
    rope_k_kernel<<<(2048 * 32 + 255) / 256, 256>>>(ckr, fcos, fsin, kcat);
    rope_q_kernel<<<(2048 * 16 * 32 + 255) / 256, 256>>>(cqr, fcos, fsin, qcat);

    // 9) q_abs -> qcat cols [0,512)
    launch_gemm(cq, keff, qcat, 1024, 512, 512,
                512, 1, 512, 1, KCAT, 32,
                16, 1024l * 512, 1, 0,
                1, 0, 16, 512l * 512,
                1, 0, 32, 1024l * KCAT);

    // 10) logits = qcat @ kcat^T  (causal tile-skip, 36/64 tiles)
    launch_gemm(qcat, kcat, attn, 1024, 1024, KCAT,
                KCAT, 1, 1, KCAT, 1024, 32,
                1, 0, 32, 1024l * KCAT,
                16, 1024l * KCAT, 1, 0,
                1, 0, 32, 1024l * 1024, 1, 1);

    // 11) softmax
    {
        dim3 grid(1024, 32);
        softmax_causal<<<grid, 256>>>(attn);
    }

    // 12) lat = attn @ c_kv  (causal k-stop)
    launch_gemm(attn, kcat, lat, 1024, 512, 1024,
                1024, 1, KCAT, 1, 512, 32,
                1, 0, 32, 1024l * 1024,
                16, 1024l * KCAT, 1, 0,
                1, 0, 32, 1024l * 512, 1, 2);

    // 13) y = lat @ veff_t^T
    launch_gemm(lat, veff, out, 1024, 128, 512,
                512, 1, 1, 512, 2048, 32,
                1, 0, 32, 1024l * 512,
                1, 0, 16, 128l * 512,
                16, 1024l * 2048, 16, 128);
}

// round 7
// speedup vs baseline: 4.5411x; 1.0769x over previous
#include <cuda_runtime.h>
#include <cuda_bf16.h>
#include <math.h>

#define BB   2
#define TT   1024
#define CC   2048
#define NH   16
#define HS   128
#define NLQ  512
#define NLKV 512
#define DHR  64
#define KCAT 576

// ---------------- scratch ----------------
__device__ float g_keff[16l * 512 * 512];       // keff_t[h][k][q] (q contiguous)
__device__ float g_veff[2048l * 512];           // veff_t[j][k]   (k contiguous)
__device__ float g_cq  [2048l * 512];
__device__ float g_ckr [2048l * 64];
__device__ float g_cqr [2048l * 1024];
__device__ float g_kcat[2048l * 576];
__device__ float g_qcat[32l * 1024 * 576];
__device__ float g_attn[32l * 1024 * 1024];
__device__ float g_lat [32l * 1024 * 512];

struct GP {
    const float* A; const float* B; float* C;
    int M, N, K;
    long sAm, sAk, sBk, sBn, ldc;
    int aDiv, aMod, bDiv, bMod, cDiv, cMod;
    long aS1, aS2, bS1, bS2, cS1, cS2;
    int kSplit;
    int mode;    // 0 plain, 1 causal tile-skip, 2 causal k-stop
};

__device__ __forceinline__ unsigned f2tf32(float x) {
    unsigned u;
    asm("cvt.rna.tf32.f32 %0, %1;" : "=r"(u) : "f"(x));
    return u;
}

__device__ __forceinline__ void mma_tf32(float* d, const unsigned* a,
                                         const unsigned* b) {
    asm volatile(
        "mma.sync.aligned.m16n8k8.row.col.f32.tf32.tf32.f32 "
        "{%0,%1,%2,%3}, {%4,%5,%6,%7}, {%8,%9}, {%0,%1,%2,%3};\n"
        : "+f"(d[0]), "+f"(d[1]), "+f"(d[2]), "+f"(d[3])
        : "r"(a[0]), "r"(a[1]), "r"(a[2]), "r"(a[3]),
          "r"(b[0]), "r"(b[1]));
}

// smem sizes (words): [k][136] layout needs 8*136=1088; [m][12] needs 128*12=1536
#define BUFW 1536

// TF32 GEMM: block 128x128, k-tile 8, 4 warps (2x2), warp tile 64x64,
// double-buffered smem (layout adapted per operand path), vectorized STS,
// split-K + causal modes.
__global__ __launch_bounds__(128) void tgemm(GP p) {
    int bmI = blockIdx.y, bnI = blockIdx.x;
    if (p.mode == 1 && bnI > bmI) return;

    int z = blockIdx.z;
    int zb = z / p.kSplit;
    int kz = z % p.kSplit;

    int kTot = p.K;
    if (p.mode == 2) { int ke = (bmI + 1) * 128; if (ke < kTot) kTot = ke; }
    int kLen = kTot / p.kSplit;

    const float* A = p.A + (long)(zb / p.aDiv) * p.aS1 + (long)(zb % p.aMod) * p.aS2
                   + (long)kz * kLen * p.sAk;
    const float* B = p.B + (long)(zb / p.bDiv) * p.bS1 + (long)(zb % p.bMod) * p.bS2
                   + (long)kz * kLen * p.sBk;
    float*       C = p.C + (long)(zb / p.cDiv) * p.cS1 + (long)(zb % p.cMod) * p.cS2;

    __shared__ __align__(16) unsigned As[2][BUFW];
    __shared__ __align__(16) unsigned Bs[2][BUFW];

    int tid  = threadIdx.x;
    int lane = tid & 31;
    int wid  = tid >> 5;
    int wm = wid >> 1, wn = wid & 1;
    int bm = bmI * 128, bn = bnI * 128;

    const bool aKc = (p.sAk == 1);
    const bool bKc = (p.sBk == 1);

    // layout strides: contiguous-K path -> [m][12]  (Sm=12, Sk=1)
    //                 non-contig path   -> [k][136] (Sm=1,  Sk=136)
    const unsigned SaM = aKc ? 12u : 1u,  SaK = aKc ? 1u : 136u;
    const unsigned SbN = bKc ? 12u : 1u,  SbK = bKc ? 1u : 136u;

    // gmem staging
    const float* aBase;  long aStep;  unsigned aOff;    // uint4 word offset (o0; o1=o0+4)
    if (aKc) {
        aBase = A + (long)(bm + tid) * p.sAm;
        aStep = 8;
        aOff  = tid * 12;
    } else {
        int k8 = tid >> 4, m0 = (tid & 15) * 8;
        aBase = A + (long)k8 * p.sAk + (bm + m0);
        aStep = 8 * p.sAk;
        aOff  = k8 * 136 + m0;
    }
    const float* bBase;  long bStep;  unsigned bOff;  bool bOk;
    if (bKc) {
        bOk = (bn + tid) < p.N;
        bBase = B + (long)(bn + tid) * p.sBn;
        bStep = 8;
        bOff  = tid * 12;
    } else {
        int k8 = tid >> 4, n0 = (tid & 15) * 8;
        bOk = (bn + n0) < p.N;
        bBase = B + (long)k8 * p.sBk + (bn + n0);
        bStep = 8 * p.sBk;
        bOff  = k8 * 136 + n0;
    }

    float ra[8], rb[8];

#define LOAD_STAGE(t)                                                        \
    {                                                                        \
        const float* ap = aBase + (long)(t) * aStep;                         \
        float4 v0 = *(const float4*)ap;                                      \
        float4 v1 = *(const float4*)(ap + 4);                                \
        ra[0]=v0.x; ra[1]=v0.y; ra[2]=v0.z; ra[3]=v0.w;                      \
        ra[4]=v1.x; ra[5]=v1.y; ra[6]=v1.z; ra[7]=v1.w;                      \
        if (bOk) {                                                           \
            const float* bp = bBase + (long)(t) * bStep;                     \
            float4 w0 = *(const float4*)bp;                                  \
            float4 w1 = *(const float4*)(bp + 4);                            \
            rb[0]=w0.x; rb[1]=w0.y; rb[2]=w0.z; rb[3]=w0.w;                  \
            rb[4]=w1.x; rb[5]=w1.y; rb[6]=w1.z; rb[7]=w1.w;                  \
        } else {                                                             \
            rb[0]=rb[1]=rb[2]=rb[3]=rb[4]=rb[5]=rb[6]=rb[7]=0.f;             \
        }                                                                    \
    }

#define STORE_STAGE(buf)                                                     \
    {                                                                        \
        uint4 va0, va1, vb0, vb1;                                            \
        va0.x=f2tf32(ra[0]); va0.y=f2tf32(ra[1]); va0.z=f2tf32(ra[2]); va0.w=f2tf32(ra[3]); \
        va1.x=f2tf32(ra[4]); va1.y=f2tf32(ra[5]); va1.z=f2tf32(ra[6]); va1.w=f2tf32(ra[7]); \
        vb0.x=f2tf32(rb[0]); vb0.y=f2tf32(rb[1]); vb0.z=f2tf32(rb[2]); vb0.w=f2tf32(rb[3]); \
        vb1.x=f2tf32(rb[4]); vb1.y=f2tf32(rb[5]); vb1.z=f2tf32(rb[6]); vb1.w=f2tf32(rb[7]); \
        *(uint4*)&As[buf][aOff]     = va0;                                   \
        *(uint4*)&As[buf][aOff + 4] = va1;                                   \
        *(uint4*)&Bs[buf][bOff]     = vb0;                                   \
        *(uint4*)&Bs[buf][bOff + 4] = vb1;                                   \
    }

    float acc[4][8][4];
#pragma unroll
    for (int i = 0; i < 4; i++)
#pragma unroll
        for (int j = 0; j < 8; j++)
#pragma unroll
            for (int r = 0; r < 4; r++) acc[i][j][r] = 0.f;

    int nt = kLen >> 3;

    LOAD_STAGE(0);
    STORE_STAGE(0);
    __syncthreads();

    int r = lane >> 2, c = lane & 3;

    // precomputed fragment word offsets (loop-invariant)
    unsigned aAddr[4], bAddr[8];
#pragma unroll
    for (int mi = 0; mi < 4; mi++)
        aAddr[mi] = (unsigned)(wm * 64 + mi * 16 + r) * SaM + (unsigned)c * SaK;
#pragma unroll
    for (int ni = 0; ni < 8; ni++)
        bAddr[ni] = (unsigned)(wn * 64 + ni * 8 + r) * SbN + (unsigned)c * SbK;
    const unsigned a8 = 8u * SaM, a4k = 4u * SaK, b4k = 4u * SbK;

    for (int t = 0; t < nt; t++) {
        int cur = t & 1;
        if (t + 1 < nt) LOAD_STAGE(t + 1);

        unsigned a[4][4], b[8][2];
#pragma unroll
        for (int mi = 0; mi < 4; mi++) {
            const unsigned* sa = &As[cur][0];
            unsigned o = aAddr[mi];
            a[mi][0] = sa[o];
            a[mi][1] = sa[o + a8];
            a[mi][2] = sa[o + a4k];
            a[mi][3] = sa[o + a8 + a4k];
        }
#pragma unroll
        for (int ni = 0; ni < 8; ni++) {
            const unsigned* sb = &Bs[cur][0];
            unsigned o = bAddr[ni];
            b[ni][0] = sb[o];
            b[ni][1] = sb[o + b4k];
        }
#pragma unroll
        for (int mi = 0; mi < 4; mi++)
#pragma unroll
            for (int ni = 0; ni < 8; ni++)
                mma_tf32(acc[mi][ni], a[mi], b[ni]);

        if (t + 1 < nt) STORE_STAGE(cur ^ 1);
        __syncthreads();
    }

    int c2 = (lane & 3) * 2;
    if (p.kSplit > 1) {
#pragma unroll
        for (int mi = 0; mi < 4; mi++) {
            int gm0 = bm + wm * 64 + mi * 16 + r;
#pragma unroll
            for (int ni = 0; ni < 8; ni++) {
                int gn = bn + wn * 64 + ni * 8 + c2;
                if (gn < p.N) {
                    atomicAdd(C + (long)gm0 * p.ldc + gn,     acc[mi][ni][0]);
                    atomicAdd(C + (long)gm0 * p.ldc + gn + 1, acc[mi][ni][1]);
                    atomicAdd(C + (long)(gm0 + 8) * p.ldc + gn,     acc[mi][ni][2]);
                    atomicAdd(C + (long)(gm0 + 8) * p.ldc + gn + 1, acc[mi][ni][3]);
                }
            }
        }
    } else {
#pragma unroll
        for (int mi = 0; mi < 4; mi++) {
            int gm0 = bm + wm * 64 + mi * 16 + r;
#pragma unroll
            for (int ni = 0; ni < 8; ni++) {
                int gn = bn + wn * 64 + ni * 8 + c2;
                if (gn < p.N) {
                    float* cp0 = C + (long)gm0 * p.ldc + gn;
                    float* cp1 = C + (long)(gm0 + 8) * p.ldc + gn;
                    cp0[0] = acc[mi][ni][0]; cp0[1] = acc[mi][ni][1];
                    cp1[0] = acc[mi][ni][2]; cp1[1] = acc[mi][ni][3];
                }
            }
        }
    }
#undef LOAD_STAGE
#undef STORE_STAGE
}

// ---------------- RoPE ----------------
__global__ void rope_k_kernel(const float* __restrict__ ckr,
                              const float* __restrict__ fc,
                              const float* __restrict__ fs,
                              float* __restrict__ kcat) {
    int idx = blockIdx.x * blockDim.x + threadIdx.x;
    if (idx >= 2048 * 32) return;
    int m = idx >> 5, i = idx & 31;
    int t = m & 1023;
    float re = ckr[m * 64 + 2 * i], im = ckr[m * 64 + 2 * i + 1];
    float c = fc[t * 32 + i], s = fs[t * 32 + i];
    long o = (long)m * KCAT + 512 + 2 * i;
    kcat[o]     = re * c - im * s;
    kcat[o + 1] = re * s + im * c;
}

__global__ void rope_q_kernel(const float* __restrict__ cqr,
                              const float* __restrict__ fc,
                              const float* __restrict__ fs,
                              float* __restrict__ qcat) {
    int idx = blockIdx.x * blockDim.x + threadIdx.x;
    if (idx >= 2048 * 16 * 32) return;
    int i = idx & 31;
    int h = (idx >> 5) & 15;
    int m = idx >> 9;
    int t = m & 1023, b = m >> 10;
    float re = cqr[m * 1024 + h * 64 + 2 * i];
    float im = cqr[m * 1024 + h * 64 + 2 * i + 1];
    float c = fc[t * 32 + i], s = fs[t * 32 + i];
    long o = ((long)((b * 16 + h) * 1024 + t)) * KCAT + 512 + 2 * i;
    qcat[o]     = re * c - im * s;
    qcat[o + 1] = re * s + im * c;
}

// ---------------- causal softmax ----------------
__global__ void softmax_causal(float* __restrict__ attn) {
    int t = blockIdx.x;
    int z = blockIdx.y;
    float* p = attn + (long)z * 1024 * 1024 + (long)t * 1024;
    int n = t + 1;
    int lim = ((t >> 7) + 1) << 7;
    const float scale = 0.07216878364870322992f * 1.44269504088896341f;
    __shared__ float red[256];
    int tid = threadIdx.x;

    float vals[4];
    float m = -3.4e38f;
#pragma unroll
    for (int j = 0; j < 4; j++) {
        int s = tid + j * 256;
        vals[j] = (s < n) ? p[s] * scale : -3.4e38f;
        m = fmaxf(m, vals[j]);
    }
    red[tid] = m; __syncthreads();
    for (int o = 128; o > 0; o >>= 1) {
        if (tid < o) red[tid] = fmaxf(red[tid], red[tid + o]);
        __syncthreads();
    }
    m = red[0]; __syncthreads();

    float sum = 0.f;
#pragma unroll
    for (int j = 0; j < 4; j++) {
        int s = tid + j * 256;
        vals[j] = (s < n) ? exp2f(vals[j] - m) : 0.f;
        sum += vals[j];
    }
    red[tid] = sum; __syncthreads();
    for (int o = 128; o > 0; o >>= 1) {
        if (tid < o) red[tid] += red[tid + o];
        __syncthreads();
    }
    float inv = 1.f / red[0];

#pragma unroll
    for (int j = 0; j < 4; j++) {
        int s = tid + j * 256;
        if (s < lim) p[s] = vals[j] * inv;
    }
}

// ---------------- launch helper ----------------
static void launch_gemm(const float* A, const float* B, float* C,
                        int M, int N, int K,
                        long sAm, long sAk, long sBk, long sBn, long ldc,
                        int batches,
                        int aDiv, long aS1, int aMod, long aS2,
                        int bDiv, long bS1, int bMod, long bS2,
                        int cDiv, long cS1, int cMod, long cS2,
                        int kSplit = 1, int mode = 0) {
    GP p;
    p.A = A; p.B = B; p.C = C;
    p.M = M; p.N = N; p.K = K;
    p.sAm = sAm; p.sAk = sAk; p.sBk = sBk; p.sBn = sBn; p.ldc = ldc;
    p.aDiv = aDiv; p.aMod = aMod; p.bDiv = bDiv; p.bMod = bMod;
    p.cDiv = cDiv; p.cMod = cMod;
    p.aS1 = aS1; p.aS2 = aS2; p.bS1 = bS1; p.bS2 = bS2; p.cS1 = cS1; p.cS2 = cS2;
    p.kSplit = kSplit; p.mode = mode;
    dim3 grid((N + 127) / 128, (M + 127) / 128, batches * kSplit);
    tgemm<<<grid, 128>>>(p);
}

extern "C" void kernel_launch(void* const* d_in, const int* in_sizes, int n_in,
                              void* d_out, int out_size) {
    const float* x     = (const float*)d_in[0];
    const float* fcos  = (const float*)d_in[1];
    const float* fsin  = (const float*)d_in[2];
    const float* W_dq  = (const float*)d_in[3];
    const float* W_uq  = (const float*)d_in[4];
    const float* W_dkv = (const float*)d_in[5];
    const float* W_uk  = (const float*)d_in[6];
    const float* W_uv  = (const float*)d_in[7];
    const float* W_qr  = (const float*)d_in[8];
    const float* W_kr  = (const float*)d_in[9];
    const float* W_o   = (const float*)d_in[10];
    float* out = (float*)d_out;

    float *keff, *veff, *cq, *ckr, *cqr, *kcat, *qcat, *attn, *lat;
    cudaGetSymbolAddress((void**)&keff, g_keff);
    cudaGetSymbolAddress((void**)&veff, g_veff);
    cudaGetSymbolAddress((void**)&cq,   g_cq);
    cudaGetSymbolAddress((void**)&ckr,  g_ckr);
    cudaGetSymbolAddress((void**)&cqr,  g_cqr);
    cudaGetSymbolAddress((void**)&kcat, g_kcat);
    cudaGetSymbolAddress((void**)&qcat, g_qcat);
    cudaGetSymbolAddress((void**)&attn, g_attn);
    cudaGetSymbolAddress((void**)&lat,  g_lat);

    cudaMemsetAsync(veff, 0, 2048l * 512 * 4);
    cudaMemsetAsync(cq,   0, 2048l * 512 * 4);
    cudaMemsetAsync(ckr,  0, 2048l * 64 * 4);
    cudaMemsetAsync(cqr,  0, 2048l * 1024 * 4);
    cudaMemsetAsync(kcat, 0, 2048l * 576 * 4);

    // 1) keff_t[h][k][q] = sum_d W_uk[(h*128+d)*512+k] * W_uq[q*2048+h*128+d]
    launch_gemm(W_uk, W_uq, keff, 512, 512, 128,
                1, 512, 1, 2048, 512, 16,
                1, 0, 16, 128l * 512,
                1, 0, 16, 128,
                1, 0, 16, 512l * 512);

    // 2) veff_t[j][k] = sum_c W_o[j*2048+c] * W_uv[c*512+k]   (split-K 4)
    launch_gemm(W_o, W_uv, veff, 2048, 512, 2048,
                2048, 1, 512, 1, 512, 1,
                1, 0, 1, 0, 1, 0, 1, 0, 1, 0, 1, 0, 4);

    // 3) c_q  (split-K 4)
    launch_gemm(x, W_dq, cq, 2048, 512, 2048,
                2048, 1, 1, 2048, 512, 1,
                1, 0, 1, 0, 1, 0, 1, 0, 1, 0, 1, 0, 4);

    // 4) c_kv -> kcat cols [0,512)  (split-K 4)
    launch_gemm(x, W_dkv, kcat, 2048, 512, 2048,
                2048, 1, 1, 2048, KCAT, 1,
                1, 0, 1, 0, 1, 0, 1, 0, 1, 0, 1, 0, 4);

    // 5) c_kr  (split-K 8)
    launch_gemm(x, W_kr, ckr, 2048, 64, 2048,
                2048, 1, 1, 2048, 64, 1,
                1, 0, 1, 0, 1, 0, 1, 0, 1, 0, 1, 0, 8);

    // 6) c_qr  (split-K 2)
    launch_gemm(cq, W_qr, cqr, 2048, 1024, 512,
                512, 1, 1, 512, 1024, 1,
                1, 0, 1, 0, 1, 0, 1, 0, 1, 0, 1, 0, 2);

    // 7-8) RoPE
    rope_k_kernel<<<(2048 * 32 + 255) / 256, 256>>>(ckr, fcos, fsin, kcat);
    rope_q_kernel<<<(2048 * 16 * 32 + 255) / 256, 256>>>(cqr, fcos, fsin, qcat);

    // 9) q_abs[t][k] = sum_q cq[t][q] * keff_t[h][k][q]  (B contiguous now)
    launch_gemm(cq, keff, qcat, 1024, 512, 512,
                512, 1, 1, 512, KCAT, 32,
                16, 1024l * 512, 1, 0,
                1, 0, 16, 512l * 512,
                1, 0, 32, 1024l * KCAT);

    // 10) logits = qcat @ kcat^T  (causal tile-skip)
    launch_gemm(qcat, kcat, attn, 1024, 1024, KCAT,
                KCAT, 1, 1, KCAT, 1024, 32,
                1, 0, 32, 1024l * KCAT,
                16, 1024l * KCAT, 1, 0,
                1, 0, 32, 1024l * 1024, 1, 1);

    // 11) softmax
    {
        dim3 grid(1024, 32);
        softmax_causal<<<grid, 256>>>(attn);
    }

    // 12) lat = attn @ c_kv  (causal k-stop; B non-contig but vectorized STS)
    launch_gemm(attn, kcat, lat, 1024, 512, 1024,
                1024, 1, KCAT, 1, 512, 32,
                1, 0, 32, 1024l * 1024,
                16, 1024l * KCAT, 1, 0,
                1, 0, 32, 1024l * 512, 1, 2);

    // 13) y = lat @ veff_t^T
    launch_gemm(lat, veff, out, 1024, 128, 512,
                512, 1, 1, 512, 2048, 32,
                1, 0, 32, 1024l * 512,
                1, 0, 16, 128l * 512,
                16, 1024l * 2048, 16, 128);
}